// round 5
// baseline (speedup 1.0000x reference)
#include <cuda_runtime.h>
#include <cuda_fp16.h>

#define TPB 512
#define T_ 200
#define D_ 64
#define H1_ 80
#define H2_ 40
#define C_ 64
#define KTS 212                  // ksT16 row stride in halves (424 B)

// ---- smem layout (bytes) ----
// ksT16 fp16 [64][212]     @ 0       (27,136 B)  — GEMM1 A + pooling
// h1    fp16 [80][200]     @ 27136   (32,000 B)
// MW    f32  [64][80]      @ 59136   (20,480 B)  — aliased by PART after GEMM1
// tail  f32/int            @ 79616
#define H1OFF 13568              // half index of h1
#define MW    14784              // float index
#define PART  14784              // alias MW
#define QA    19904
#define WGT   19984
#define RED   20184
#define PA1   20216
#define PB2   20296
#define PA2   20336
#define PWF   20376
#define QS    20416
#define CATE  20480
#define CNT   20680
#define CNT2  20744
#define BST   20808
#define TLIST 20872
#define SMEM_FLOATS 21072
#define SMEM_BYTES (SMEM_FLOATS * 4)   // 84,288 B -> 2 CTAs/SM

typedef unsigned long long ull;

__device__ __forceinline__ ull ffma2(ull a, ull b, ull c) {
    ull d;
    asm("fma.rn.f32x2 %0, %1, %2, %3;" : "=l"(d) : "l"(a), "l"(b), "l"(c));
    return d;
}
__device__ __forceinline__ ull dup2(float x) {
    ull r;
    asm("mov.b64 %0, {%1, %1};" : "=l"(r) : "f"(x));
    return r;
}
__device__ __forceinline__ float2 unpk(ull v) {
    float2 f;
    asm("mov.b64 {%0, %1}, %2;" : "=f"(f.x), "=f"(f.y) : "l"(v));
    return f;
}

__global__ __launch_bounds__(TPB, 2)
void din_kernel(const float* __restrict__ q, const float* __restrict__ k,
                const int* __restrict__ mask, const int* __restrict__ cate,
                const float* __restrict__ W1, const float* __restrict__ b1,
                const float* __restrict__ a1, const float* __restrict__ W2,
                const float* __restrict__ b2, const float* __restrict__ a2,
                const float* __restrict__ Wf, const float* __restrict__ bf,
                float* __restrict__ out_ui, float* __restrict__ out_ch)
{
    extern __shared__ float sm[];
    int* smi = (int*)sm;
    __half* sh = (__half*)sm;                 // ksT16 at sh[0], h1 at sh[H1OFF]
    const int b = blockIdx.x;
    const int tid = threadIdx.x;
    const int lane = tid & 31, warp = tid >> 5;

    // ---------------- Phase 0: params + fp16 transpose of k ----------------
    if (tid < D_)  sm[QS + tid]  = q[b * D_ + tid];
    if (tid < H1_) sm[PA1 + tid] = a1[tid];
    if (tid < H2_) { sm[PB2 + tid] = b2[tid]; sm[PA2 + tid] = a2[tid]; sm[PWF + tid] = Wf[tid]; }
    if (tid < T_)  smi[CATE + tid] = cate[b * T_ + tid];
    if (tid < C_)  smi[CNT + tid] = 0;
    // warp w owns dims d0..d0+3; lanes take even t pairs -> conflict-free STS.32
    {
        const float4* k4 = (const float4*)(k + (size_t)b * T_ * D_);
        const int d0 = warp * 4;
        for (int tp = lane; tp < 100; tp += 32) {
            const int t = tp * 2;
            float4 v0 = k4[t * 16 + warp];
            float4 v1 = k4[(t + 1) * 16 + warp];
            *(__half2*)&sh[(d0    ) * KTS + t] = __floats2half2_rn(v0.x, v1.x);
            *(__half2*)&sh[(d0 + 1) * KTS + t] = __floats2half2_rn(v0.y, v1.y);
            *(__half2*)&sh[(d0 + 2) * KTS + t] = __floats2half2_rn(v0.z, v1.z);
            *(__half2*)&sh[(d0 + 3) * KTS + t] = __floats2half2_rn(v0.w, v1.w);
        }
    }
    __syncthreads();

    // ---------------- Phase 1: folded weight M (f32), qa bias, bucket counts ----------
    // info@W1 = qa + k_t @ M,  M = W1b - W1c + diag(q) W1d,  qa = q@(W1a+W1c)+b1
    for (int e = tid; e < D_ * H1_; e += TPB) {
        int d = e / H1_, h = e - d * H1_;
        sm[MW + e] = W1[(64 + d) * H1_ + h] - W1[(128 + d) * H1_ + h]
                   + sm[QS + d] * W1[(192 + d) * H1_ + h];
    }
    if (tid < 320) {
        const int h = tid >> 2, qq = tid & 3;
        float s = 0.f;
        const int d0 = qq * 16;
#pragma unroll 4
        for (int d = d0; d < d0 + 16; ++d)
            s += sm[QS + d] * (W1[d * H1_ + h] + W1[(128 + d) * H1_ + h]);
        s += __shfl_xor_sync(0xffffffffu, s, 1);
        s += __shfl_xor_sync(0xffffffffu, s, 2);
        if (qq == 0) sm[QA + h] = s + b1[h];
    }
    if (tid < T_) atomicAdd(&smi[CNT + smi[CATE + tid]], 1);
    __syncthreads();

    // ---------------- Phase 2: GEMM1 [200,64]@[64,80] + PReLU -> h1 fp16 --------------
    if (tid < 500) {
        const int tt = tid % 50, hh = tid / 50;
        const int t0 = tt * 4, h0 = hh * 8;
        ull acc[4][4];   // [t][h-pair]
#pragma unroll
        for (int i = 0; i < 4; ++i)
#pragma unroll
            for (int j = 0; j < 4; ++j) acc[i][j] = 0ull;

#pragma unroll 4
        for (int d = 0; d < D_; ++d) {
            const uint2 ka = *(const uint2*)&sh[d * KTS + t0];                  // 4 halves, 2 wf
            const ulonglong2 mA = *(const ulonglong2*)&sm[MW + d * H1_ + h0];      // bcast
            const ulonglong2 mB = *(const ulonglong2*)&sm[MW + d * H1_ + h0 + 4];  // bcast
            float2 f01 = __half22float2(*(__half2*)&ka.x);
            float2 f23 = __half22float2(*(__half2*)&ka.y);
            ull kd[4] = {dup2(f01.x), dup2(f01.y), dup2(f23.x), dup2(f23.y)};
            ull mp[4] = {mA.x, mA.y, mB.x, mB.y};
#pragma unroll
            for (int i = 0; i < 4; ++i)
#pragma unroll
                for (int j = 0; j < 4; ++j) acc[i][j] = ffma2(kd[i], mp[j], acc[i][j]);
        }
#pragma unroll
        for (int j = 0; j < 4; ++j) {          // h-pairs
#pragma unroll
            for (int p = 0; p < 2; ++p) {
                const int h = h0 + 2 * j + p;
                const float bias = sm[QA + h];
                const float al   = sm[PA1 + h];
                float o[4];
#pragma unroll
                for (int i = 0; i < 4; ++i) {
                    float2 v2 = unpk(acc[i][j]);
                    float v = (p == 0 ? v2.x : v2.y) + bias;
                    o[i] = (v > 0.f) ? v : al * v;
                }
                __half2 q01 = __float22half2_rn(make_float2(o[0], o[1]));
                __half2 q23 = __float22half2_rn(make_float2(o[2], o[3]));
                *(uint2*)&sh[H1OFF + h * T_ + t0] =
                    make_uint2(*(unsigned*)&q01, *(unsigned*)&q23);
            }
        }
    }
    __syncthreads();

    // ---------------- Phase 3: GEMM2 [200,80]@[80,40] + PReLU + Wf dot ----------------
    if (tid < 500) {
        const int tt = tid % 50, hh = tid / 50;
        const int t0 = tt * 4, j0 = hh * 4;
        ull acc2[4][2];  // [t][j-pair]
#pragma unroll
        for (int i = 0; i < 4; ++i) { acc2[i][0] = 0ull; acc2[i][1] = 0ull; }

#pragma unroll 4
        for (int dd = 0; dd < H1_; ++dd) {
            const uint2 hp = *(const uint2*)&sh[H1OFF + dd * T_ + t0];          // 2 wf
            const ulonglong2 wv = *(const ulonglong2*)&W2[dd * H2_ + j0];       // L1-hit LDG
            float2 f0 = __half22float2(*(__half2*)&hp.x);
            float2 f1 = __half22float2(*(__half2*)&hp.y);
            ull td[4] = {dup2(f0.x), dup2(f0.y), dup2(f1.x), dup2(f1.y)};
#pragma unroll
            for (int i = 0; i < 4; ++i) {
                acc2[i][0] = ffma2(td[i], wv.x, acc2[i][0]);
                acc2[i][1] = ffma2(td[i], wv.y, acc2[i][1]);
            }
        }
        float pl[4] = {0.f, 0.f, 0.f, 0.f};
#pragma unroll
        for (int jp = 0; jp < 2; ++jp) {
#pragma unroll
            for (int p = 0; p < 2; ++p) {
                const int j = j0 + 2 * jp + p;
                const float bb = sm[PB2 + j];
                const float al = sm[PA2 + j];
                const float wf = sm[PWF + j];
#pragma unroll
                for (int i = 0; i < 4; ++i) {
                    float2 v2 = unpk(acc2[i][jp]);
                    float x = (p == 0 ? v2.x : v2.y) + bb;
                    x = (x > 0.f) ? x : al * x;
                    pl[i] += x * wf;
                }
            }
        }
        *(float4*)&sm[PART + hh * T_ + t0] = make_float4(pl[0], pl[1], pl[2], pl[3]);
    }
    __syncthreads();

    // ---------------- Phase 4: logits + mask; warp15: bucket prefix scan -------------
    if (tid < T_) {
        float s = bf[0];
#pragma unroll
        for (int g = 0; g < 10; ++g) s += sm[PART + g * T_ + tid];
        if (mask[b * T_ + tid] == 0) s = -4294967295.0f;   // -2^32 + 1
        sm[WGT + tid] = s * 0.125f;                         // / sqrt(64)
    }
    if (tid >= 480) {
        const int l = tid - 480;
        const int c0 = smi[CNT + 2 * l], c1 = smi[CNT + 2 * l + 1];
        int s = c0 + c1;
#pragma unroll
        for (int off = 1; off < 32; off <<= 1) {
            int n = __shfl_up_sync(0xffffffffu, s, off);
            if (l >= off) s += n;
        }
        const int excl = s - (c0 + c1);
        smi[BST + 2 * l] = excl;        smi[BST + 2 * l + 1] = excl + c0;
        smi[CNT2 + 2 * l] = excl;       smi[CNT2 + 2 * l + 1] = excl + c0;
    }
    __syncthreads();

    // ---------------- Phase 5: softmax over 200 ----------------
    {
        float v = (tid < T_) ? sm[WGT + tid] : -3.4e38f;
#pragma unroll
        for (int o = 16; o; o >>= 1) v = fmaxf(v, __shfl_xor_sync(0xffffffffu, v, o));
        if (lane == 0) sm[RED + warp] = v;
        __syncthreads();
        float mx = sm[RED + 0];
#pragma unroll
        for (int i = 1; i < 16; ++i) mx = fmaxf(mx, sm[RED + i]);
        float e = (tid < T_) ? __expf(sm[WGT + tid] - mx) : 0.f;
        float sv = e;
#pragma unroll
        for (int o = 16; o; o >>= 1) sv += __shfl_xor_sync(0xffffffffu, sv, o);
        if (lane == 0) sm[RED + 16 + warp] = sv;
        __syncthreads();
        float S = 0.f;
#pragma unroll
        for (int i = 0; i < 16; ++i) S += sm[RED + 16 + i];
        if (tid < T_) sm[WGT + tid] = e / S;
    }
    __syncthreads();

    // ---------------- Phase 5b+6: bucket scatter + user_interest partials ------------
    if (tid < T_) {
        const int c = smi[CATE + tid];
        const int pos = atomicAdd(&smi[CNT2 + c], 1);
        smi[TLIST + pos] = tid;
    }
    {
        const int d = tid & 63, g = tid >> 6;   // 8 groups x 25 t; <=2-way conflict reads
        float s = 0.f;
        const int tb = g * 25;
#pragma unroll 5
        for (int t = tb; t < tb + 25; ++t)
            s += sm[WGT + t] * __half2float(sh[d * KTS + t]);
        sm[PART + tid] = s;
    }
    __syncthreads();

    if (tid < D_) {
        float s = 0.f;
#pragma unroll
        for (int g = 0; g < 8; ++g) s += sm[PART + g * 64 + tid];
        out_ui[b * D_ + tid] = s;
    }

    // ---------------- Phase 7: bucketed per-category pooling (no atomics) ------------
    {
        const int g = tid >> 6, d = tid & 63;   // 8 groups of 64 lanes; 8 cats each
        float* ch = out_ch + (size_t)b * C_ * D_;
        for (int c = g; c < C_; c += 8) {
            const int len = smi[CNT + c];
            const int st  = smi[BST + c];
            float acc = 0.f, ws = 0.f;
            for (int i = 0; i < len; ++i) {
                const int t = smi[TLIST + st + i];
                const float w = sm[WGT + t];
                ws  += w;
                acc += w * __half2float(sh[d * KTS + t]);
            }
            ch[c * D_ + d] = acc / (ws + 1e-10f);
        }
    }
}

extern "C" void kernel_launch(void* const* d_in, const int* in_sizes, int n_in,
                              void* d_out, int out_size)
{
    const float* q    = (const float*)d_in[0];
    const float* k    = (const float*)d_in[1];
    const int*   mask = (const int*)d_in[2];
    const int*   cate = (const int*)d_in[3];
    // d_in[4] = cate_count (compile-time C_=64)
    const float* W1 = (const float*)d_in[5];
    const float* b1 = (const float*)d_in[6];
    const float* a1 = (const float*)d_in[7];
    const float* W2 = (const float*)d_in[8];
    const float* b2 = (const float*)d_in[9];
    const float* a2 = (const float*)d_in[10];
    const float* Wf = (const float*)d_in[11];
    const float* bf = (const float*)d_in[12];

    const int B = in_sizes[0] / D_;
    float* out_ui = (float*)d_out;                     // [B, 64]
    float* out_ch = (float*)d_out + (size_t)B * D_;    // [B, 64, 64]

    cudaFuncSetAttribute(din_kernel, cudaFuncAttributeMaxDynamicSharedMemorySize, SMEM_BYTES);
    din_kernel<<<B, TPB, SMEM_BYTES>>>(q, k, mask, cate, W1, b1, a1, W2, b2, a2, Wf, bf,
                                       out_ui, out_ch);
}

// round 7
// speedup vs baseline: 1.7088x; 1.7088x over previous
#include <cuda_runtime.h>
#include <cuda_fp16.h>
#include <cstdint>

#define TPB 512
#define T_ 200
#define D_ 64
#define H1_ 80
#define H2_ 40
#define C_ 64

// ---- smem half-index layout ----
#define KH   0            // k fp16 [208][72]   (29,952 B)
#define KS   72
#define H1H  14976        // h1 fp16 [208][88]  (36,608 B)
#define HS   88
#define MTH  33280        // M^T fp16 [80][72]  (11,520 B)
#define W2H  39040        // W2^T fp16 [40][88] ( 7,040 B)
// ---- float-index tail (byte 85120) ----
#define QA    21280
#define PA1   21360
#define PB2   21440
#define PA2   21480
#define PWF   21520
#define QS    21560
#define WGT   21624
#define RED   21824
#define PART  21856
#define CATE  22368
#define CNT   22568
#define CNT2  22632
#define BST   22696
#define TLIST 22760
#define SMEM_FLOATS 22960
#define SMEM_BYTES (SMEM_FLOATS * 4)   // 91,840 B -> 2 CTAs/SM

__device__ __forceinline__ void mma16816(float* c, uint32_t a0, uint32_t a1,
                                         uint32_t a2, uint32_t a3,
                                         uint32_t b0, uint32_t b1) {
    asm volatile(
        "mma.sync.aligned.m16n8k16.row.col.f32.f16.f16.f32 "
        "{%0,%1,%2,%3}, {%4,%5,%6,%7}, {%8,%9}, {%0,%1,%2,%3};"
        : "+f"(c[0]), "+f"(c[1]), "+f"(c[2]), "+f"(c[3])
        : "r"(a0), "r"(a1), "r"(a2), "r"(a3), "r"(b0), "r"(b1));
}

__global__ __launch_bounds__(TPB, 2)
void din_kernel(const float* __restrict__ q, const float* __restrict__ k,
                const int* __restrict__ mask, const int* __restrict__ cate,
                const float* __restrict__ W1, const float* __restrict__ b1,
                const float* __restrict__ a1, const float* __restrict__ W2,
                const float* __restrict__ b2, const float* __restrict__ a2,
                const float* __restrict__ Wf, const float* __restrict__ bf,
                float* __restrict__ out_ui, float* __restrict__ out_ch)
{
    extern __shared__ float sm[];
    int* smi = (int*)sm;
    __half* sh = (__half*)sm;
    const int b = blockIdx.x;
    const int tid = threadIdx.x;
    const int lane = tid & 31, warp = tid >> 5;

    // ---------------- Phase 0: params, k->fp16, W2^T ----------------
    if (tid < D_)  sm[QS + tid]  = q[b * D_ + tid];
    if (tid < H1_) sm[PA1 + tid] = a1[tid];
    if (tid < H2_) { sm[PB2 + tid] = b2[tid]; sm[PA2 + tid] = a2[tid]; sm[PWF + tid] = Wf[tid]; }
    if (tid < T_)  smi[CATE + tid] = cate[b * T_ + tid];
    if (tid < C_)  smi[CNT + tid] = 0;
    {
        const float4* k4 = (const float4*)(k + (size_t)b * T_ * D_);
        for (int idx = tid; idx < T_ * 16; idx += TPB) {
            float4 v = k4[idx];
            const int t = idx >> 4, f4 = idx & 15;
            uint2 u;
            *(__half2*)&u.x = __floats2half2_rn(v.x, v.y);
            *(__half2*)&u.y = __floats2half2_rn(v.z, v.w);
            *(uint2*)&sh[t * KS + f4 * 4] = u;
        }
        if (tid < 128) {                       // zero-pad rows 200..207
            const int t = 200 + (tid >> 4), d4 = (tid & 15) * 4;
            *(uint2*)&sh[t * KS + d4] = make_uint2(0u, 0u);
        }
    }
    for (int i = tid; i < H1_ * H2_; i += TPB) {       // W2^T [40][88]
        const int dd = i / H2_, j = i - dd * H2_;
        sh[W2H + j * HS + dd] = __float2half_rn(W2[i]);
    }
    __syncthreads();

    // ---------------- Phase 1: M^T fp16, qa bias, bucket counts ----------------
    // info@W1 = qa + k @ M,  M[d][h] = W1b - W1c + q_d*W1d,  qa = q@(W1a+W1c)+b1
    for (int i = tid; i < D_ * H1_; i += TPB) {
        const int d = i / H1_, h = i - d * H1_;
        float m = W1[(64 + d) * H1_ + h] - W1[(128 + d) * H1_ + h]
                + sm[QS + d] * W1[(192 + d) * H1_ + h];
        sh[MTH + h * KS + d] = __float2half_rn(m);
    }
    if (tid < 320) {
        const int h = tid >> 2, qq = tid & 3;
        float s = 0.f;
        const int d0 = qq * 16;
#pragma unroll 4
        for (int d = d0; d < d0 + 16; ++d)
            s += sm[QS + d] * (W1[d * H1_ + h] + W1[(128 + d) * H1_ + h]);
        s += __shfl_xor_sync(0xffffffffu, s, 1);
        s += __shfl_xor_sync(0xffffffffu, s, 2);
        if (qq == 0) sm[QA + h] = s + b1[h];
    }
    if (tid < T_) atomicAdd(&smi[CNT + smi[CATE + tid]], 1);
    __syncthreads();

    // ---------------- GEMM1 (HMMA): h1 = PReLU(k @ M + qa) ----------------
    if (warp < 13) {
        const int mt = warp;
        const int r = lane >> 2, qd = lane & 3;
#pragma unroll
        for (int hf = 0; hf < 2; ++hf) {
            float acc[5][4];
#pragma unroll
            for (int n5 = 0; n5 < 5; ++n5)
#pragma unroll
                for (int x = 0; x < 4; ++x) acc[n5][x] = 0.f;
#pragma unroll
            for (int kk = 0; kk < 4; ++kk) {
                const int cm = qd * 2 + kk * 16;
                const uint32_t a0 = *(const uint32_t*)&sh[(mt * 16 + r    ) * KS + cm];
                const uint32_t a1 = *(const uint32_t*)&sh[(mt * 16 + r + 8) * KS + cm];
                const uint32_t a2 = *(const uint32_t*)&sh[(mt * 16 + r    ) * KS + cm + 8];
                const uint32_t a3 = *(const uint32_t*)&sh[(mt * 16 + r + 8) * KS + cm + 8];
#pragma unroll
                for (int n5 = 0; n5 < 5; ++n5) {
                    const int nn = (hf * 5 + n5) * 8 + r;
                    const uint32_t b0 = *(const uint32_t*)&sh[MTH + nn * KS + cm];
                    const uint32_t b1 = *(const uint32_t*)&sh[MTH + nn * KS + cm + 8];
                    mma16816(acc[n5], a0, a1, a2, a3, b0, b1);
                }
            }
#pragma unroll
            for (int n5 = 0; n5 < 5; ++n5) {
                const int j = (hf * 5 + n5) * 8 + qd * 2;
                const float q0 = sm[QA + j],  q1 = sm[QA + j + 1];
                const float l0 = sm[PA1 + j], l1 = sm[PA1 + j + 1];
                float v0 = acc[n5][0] + q0; v0 = (v0 > 0.f) ? v0 : v0 * l0;
                float v1 = acc[n5][1] + q1; v1 = (v1 > 0.f) ? v1 : v1 * l1;
                float v2 = acc[n5][2] + q0; v2 = (v2 > 0.f) ? v2 : v2 * l0;
                float v3 = acc[n5][3] + q1; v3 = (v3 > 0.f) ? v3 : v3 * l1;
                __half2 hlo = __floats2half2_rn(v0, v1);
                __half2 hhi = __floats2half2_rn(v2, v3);
                *(__half2*)&sh[H1H + (mt * 16 + r    ) * HS + j] = hlo;
                *(__half2*)&sh[H1H + (mt * 16 + r + 8) * HS + j] = hhi;
            }
        }
    }
    __syncthreads();

    // ---------------- GEMM2 (HMMA) + logits; warp15: bucket scan ----------------
    if (warp < 13) {
        const int mt = warp;
        const int r = lane >> 2, qd = lane & 3;
        float acc[5][4];
#pragma unroll
        for (int jn = 0; jn < 5; ++jn)
#pragma unroll
            for (int x = 0; x < 4; ++x) acc[jn][x] = 0.f;
#pragma unroll
        for (int kk = 0; kk < 5; ++kk) {
            const int cm = qd * 2 + kk * 16;
            const uint32_t a0 = *(const uint32_t*)&sh[H1H + (mt * 16 + r    ) * HS + cm];
            const uint32_t a1 = *(const uint32_t*)&sh[H1H + (mt * 16 + r + 8) * HS + cm];
            const uint32_t a2 = *(const uint32_t*)&sh[H1H + (mt * 16 + r    ) * HS + cm + 8];
            const uint32_t a3 = *(const uint32_t*)&sh[H1H + (mt * 16 + r + 8) * HS + cm + 8];
#pragma unroll
            for (int jn = 0; jn < 5; ++jn) {
                const int nn = jn * 8 + r;
                const uint32_t b0 = *(const uint32_t*)&sh[W2H + nn * HS + cm];
                const uint32_t b1 = *(const uint32_t*)&sh[W2H + nn * HS + cm + 8];
                mma16816(acc[jn], a0, a1, a2, a3, b0, b1);
            }
        }
        float slo = 0.f, shi = 0.f;
#pragma unroll
        for (int jn = 0; jn < 5; ++jn) {
            const int j = jn * 8 + qd * 2;
            const float bb0 = sm[PB2 + j], bb1 = sm[PB2 + j + 1];
            const float al0 = sm[PA2 + j], al1 = sm[PA2 + j + 1];
            const float wf0 = sm[PWF + j], wf1 = sm[PWF + j + 1];
            float x0 = acc[jn][0] + bb0; x0 = (x0 > 0.f) ? x0 : x0 * al0;
            float x1 = acc[jn][1] + bb1; x1 = (x1 > 0.f) ? x1 : x1 * al1;
            float x2 = acc[jn][2] + bb0; x2 = (x2 > 0.f) ? x2 : x2 * al0;
            float x3 = acc[jn][3] + bb1; x3 = (x3 > 0.f) ? x3 : x3 * al1;
            slo += x0 * wf0 + x1 * wf1;
            shi += x2 * wf0 + x3 * wf1;
        }
        slo += __shfl_xor_sync(0xffffffffu, slo, 1);
        slo += __shfl_xor_sync(0xffffffffu, slo, 2);
        shi += __shfl_xor_sync(0xffffffffu, shi, 1);
        shi += __shfl_xor_sync(0xffffffffu, shi, 2);
        if (qd == 0) {
            const float bff = bf[0];
            const int t0 = mt * 16 + r, t1 = t0 + 8;
            if (t0 < T_) {
                float s = slo + bff;
                if (mask[b * T_ + t0] == 0) s = -4294967295.0f;
                sm[WGT + t0] = s * 0.125f;
            }
            if (t1 < T_) {
                float s = shi + bff;
                if (mask[b * T_ + t1] == 0) s = -4294967295.0f;
                sm[WGT + t1] = s * 0.125f;
            }
        }
    }
    if (tid >= 480) {   // warp 15: bucket prefix scan (CNT final since phase-1 sync)
        const int l = tid - 480;
        const int c0 = smi[CNT + 2 * l], c1 = smi[CNT + 2 * l + 1];
        int s = c0 + c1;
#pragma unroll
        for (int off = 1; off < 32; off <<= 1) {
            int n = __shfl_up_sync(0xffffffffu, s, off);
            if (l >= off) s += n;
        }
        const int excl = s - (c0 + c1);
        smi[BST + 2 * l] = excl;        smi[BST + 2 * l + 1] = excl + c0;
        smi[CNT2 + 2 * l] = excl;       smi[CNT2 + 2 * l + 1] = excl + c0;
    }
    __syncthreads();

    // ---------------- Softmax over 200 ----------------
    {
        float v = (tid < T_) ? sm[WGT + tid] : -3.4e38f;
#pragma unroll
        for (int o = 16; o; o >>= 1) v = fmaxf(v, __shfl_xor_sync(0xffffffffu, v, o));
        if (lane == 0) sm[RED + warp] = v;
        __syncthreads();
        float mx = sm[RED + 0];
#pragma unroll
        for (int i = 1; i < 16; ++i) mx = fmaxf(mx, sm[RED + i]);
        float e = (tid < T_) ? __expf(sm[WGT + tid] - mx) : 0.f;
        float sv = e;
#pragma unroll
        for (int o = 16; o; o >>= 1) sv += __shfl_xor_sync(0xffffffffu, sv, o);
        if (lane == 0) sm[RED + 16 + warp] = sv;
        __syncthreads();
        float S = 0.f;
#pragma unroll
        for (int i = 0; i < 16; ++i) S += sm[RED + 16 + i];
        if (tid < T_) sm[WGT + tid] = e / S;
    }
    __syncthreads();

    // ---------------- Bucket scatter + user_interest partials ----------------
    if (tid < T_) {
        const int c = smi[CATE + tid];
        const int pos = atomicAdd(&smi[CNT2 + c], 1);
        smi[TLIST + pos] = tid;
    }
    {
        const int d = tid & 63, g = tid >> 6;   // 8 groups x 25 t; row reads conflict-free
        float s = 0.f;
        const int tb = g * 25;
#pragma unroll 5
        for (int t = tb; t < tb + 25; ++t)
            s += sm[WGT + t] * __half2float(sh[t * KS + d]);
        sm[PART + tid] = s;
    }
    __syncthreads();

    if (tid < D_) {
        float s = 0.f;
#pragma unroll
        for (int g = 0; g < 8; ++g) s += sm[PART + g * 64 + tid];
        out_ui[b * D_ + tid] = s;
    }

    // ---------------- Bucketed per-category pooling (no atomics) ----------------
    {
        const int g = tid >> 6, d = tid & 63;
        float* ch = out_ch + (size_t)b * C_ * D_;
        for (int c = g; c < C_; c += 8) {
            const int len = smi[CNT + c];
            const int st  = smi[BST + c];
            float acc = 0.f, ws = 0.f;
            for (int i = 0; i < len; ++i) {
                const int t = smi[TLIST + st + i];
                const float w = sm[WGT + t];
                ws  += w;
                acc += w * __half2float(sh[t * KS + d]);
            }
            ch[c * D_ + d] = acc / (ws + 1e-10f);
        }
    }
}

extern "C" void kernel_launch(void* const* d_in, const int* in_sizes, int n_in,
                              void* d_out, int out_size)
{
    const float* q    = (const float*)d_in[0];
    const float* k    = (const float*)d_in[1];
    const int*   mask = (const int*)d_in[2];
    const int*   cate = (const int*)d_in[3];
    // d_in[4] = cate_count (compile-time C_=64)
    const float* W1 = (const float*)d_in[5];
    const float* b1 = (const float*)d_in[6];
    const float* a1 = (const float*)d_in[7];
    const float* W2 = (const float*)d_in[8];
    const float* b2 = (const float*)d_in[9];
    const float* a2 = (const float*)d_in[10];
    const float* Wf = (const float*)d_in[11];
    const float* bf = (const float*)d_in[12];

    const int B = in_sizes[0] / D_;
    float* out_ui = (float*)d_out;                     // [B, 64]
    float* out_ch = (float*)d_out + (size_t)B * D_;    // [B, 64, 64]

    cudaFuncSetAttribute(din_kernel, cudaFuncAttributeMaxDynamicSharedMemorySize, SMEM_BYTES);
    din_kernel<<<B, TPB, SMEM_BYTES>>>(q, k, mask, cate, W1, b1, a1, W2, b2, a2, Wf, bf,
                                       out_ui, out_ch);
}

// round 8
// speedup vs baseline: 1.9125x; 1.1192x over previous
#include <cuda_runtime.h>
#include <cuda_fp16.h>
#include <cstdint>

#define TPB 512
#define T_ 200
#define D_ 64
#define H1_ 80
#define H2_ 40
#define C_ 64
#define BMAX 4096

// ---- smem half-index layout ----
#define KH   0            // k fp16 [208][72]   (29,952 B)
#define KS   72
#define H1H  14976        // h1 fp16 [208][88]  (36,608 B)
#define HS   88
#define MTH  33280        // M^T fp16 [80][72]  (11,520 B)
#define W2H  39040        // W2^T fp16 [40][88] ( 7,040 B)
// ---- float-index tail (byte 85120) ----
#define QA    21280
#define PA1   21360
#define PB2   21440
#define PA2   21480
#define PWF   21520
#define WGT   21624
#define RED   21824
#define PART  21856
#define CATE  22368
#define CNT   22568
#define CNT2  22632
#define BST   22696
#define TLIST 22760
#define SMEM_FLOATS 22960
#define SMEM_BYTES (SMEM_FLOATS * 4)   // 91,840 B -> 2 CTAs/SM

// ---- device-global prepped weights ----
__device__ __align__(16) __half g_w1bc[H1_ * D_];   // (W1b - W1c)^T  [h][d]
__device__ __align__(16) __half g_w1d [H1_ * D_];   // W1d^T          [h][d]
__device__ __align__(16) __half g_w2t [H2_ * HS];   // W2^T padded    [j][88]
__device__ float g_qa[BMAX * H1_];                  // qa = q@(W1a+W1c)+b1

__device__ __forceinline__ void mma16816(float* c, uint32_t a0, uint32_t a1,
                                         uint32_t a2, uint32_t a3,
                                         uint32_t b0, uint32_t b1) {
    asm volatile(
        "mma.sync.aligned.m16n8k16.row.col.f32.f16.f16.f32 "
        "{%0,%1,%2,%3}, {%4,%5,%6,%7}, {%8,%9}, {%0,%1,%2,%3};"
        : "+f"(c[0]), "+f"(c[1]), "+f"(c[2]), "+f"(c[3])
        : "r"(a0), "r"(a1), "r"(a2), "r"(a3), "r"(b0), "r"(b1));
}
__device__ __forceinline__ void ldm_x4(uint32_t* r, uint32_t addr) {
    asm volatile("ldmatrix.sync.aligned.m8n8.x4.shared.b16 {%0,%1,%2,%3}, [%4];"
        : "=r"(r[0]), "=r"(r[1]), "=r"(r[2]), "=r"(r[3]) : "r"(addr));
}
__device__ __forceinline__ void ldm_x2(uint32_t* r, uint32_t addr) {
    asm volatile("ldmatrix.sync.aligned.m8n8.x2.shared.b16 {%0,%1}, [%2];"
        : "=r"(r[0]), "=r"(r[1]) : "r"(addr));
}
__device__ __forceinline__ uint32_t sptr(const void* p) {
    return (uint32_t)__cvta_generic_to_shared(p);
}

// ---------- prep kernels (batch-invariant weight transforms) ----------
__global__ void prep_w(const float* __restrict__ W1, const float* __restrict__ W2) {
    const int g = blockIdx.x * blockDim.x + threadIdx.x;
    const int stride = gridDim.x * blockDim.x;
    for (int i = g; i < H1_ * D_; i += stride) {
        const int h = i >> 6, d = i & 63;
        g_w1bc[i] = __float2half_rn(W1[(64 + d) * H1_ + h] - W1[(128 + d) * H1_ + h]);
        g_w1d[i]  = __float2half_rn(W1[(192 + d) * H1_ + h]);
    }
    for (int i = g; i < H2_ * HS; i += stride) {
        const int j = i / HS, c = i - j * HS;
        g_w2t[i] = (c < H1_) ? __float2half_rn(W2[c * H2_ + j]) : __float2half_rn(0.f);
    }
}

__global__ void prep_qa(const float* __restrict__ q, const float* __restrict__ W1,
                        const float* __restrict__ b1, int B) {
    __shared__ float ws[D_ * H1_];
    const int tid = threadIdx.x;
    for (int i = tid; i < D_ * H1_; i += 256) {
        const int d = i / H1_, h = i - d * H1_;
        ws[i] = W1[d * H1_ + h] + W1[(128 + d) * H1_ + h];
    }
    __syncthreads();
    const int b0 = blockIdx.x * 16;
    for (int o = tid; o < 16 * H1_; o += 256) {
        const int bb = b0 + o / H1_, h = o % H1_;
        if (bb < B) {
            float s = b1[h];
            const float* qr = q + bb * D_;
#pragma unroll 8
            for (int d = 0; d < D_; ++d) s += qr[d] * ws[d * H1_ + h];
            g_qa[bb * H1_ + h] = s;
        }
    }
}

// ---------------------------- main kernel ----------------------------
__global__ __launch_bounds__(TPB, 2)
void din_kernel(const float* __restrict__ q, const float* __restrict__ k,
                const int* __restrict__ mask, const int* __restrict__ cate,
                const float* __restrict__ a1, const float* __restrict__ b2,
                const float* __restrict__ a2, const float* __restrict__ Wf,
                const float* __restrict__ bf,
                float* __restrict__ out_ui, float* __restrict__ out_ch)
{
    extern __shared__ float sm[];
    int* smi = (int*)sm;
    __half* sh = (__half*)sm;
    const int b = blockIdx.x;
    const int tid = threadIdx.x;
    const int lane = tid & 31, warp = tid >> 5;

    // ---------------- Phase 0+1 (merged): params, k->fp16, W2^T, M^T, qa -------------
    if (tid < H1_) { sm[QA + tid] = g_qa[b * H1_ + tid]; sm[PA1 + tid] = a1[tid]; }
    if (tid < H2_) { sm[PB2 + tid] = b2[tid]; sm[PA2 + tid] = a2[tid]; sm[PWF + tid] = Wf[tid]; }
    if (tid < T_)  smi[CATE + tid] = cate[b * T_ + tid];
    if (tid < C_)  smi[CNT + tid] = 0;
    {   // k -> fp16 [208][72]
        const float4* k4 = (const float4*)(k + (size_t)b * T_ * D_);
        for (int idx = tid; idx < T_ * 16; idx += TPB) {
            float4 v = k4[idx];
            const int t = idx >> 4, f4 = idx & 15;
            uint2 u;
            *(__half2*)&u.x = __floats2half2_rn(v.x, v.y);
            *(__half2*)&u.y = __floats2half2_rn(v.z, v.w);
            *(uint2*)&sh[t * KS + f4 * 4] = u;
        }
        if (tid < 128) {                       // zero-pad rows 200..207
            const int t = 200 + (tid >> 4), d4 = (tid & 15) * 4;
            *(uint2*)&sh[t * KS + d4] = make_uint2(0u, 0u);
        }
    }
    {   // W2^T pre-padded copy: 440 uint4
        const uint4* w2g = (const uint4*)g_w2t;
        uint4* w2s = (uint4*)&sh[W2H];
        if (tid < 440) w2s[tid] = w2g[tid];
    }
    {   // M^T[h][d] = w1bc + q_d * w1d  (fp16 in, f32 fma, fp16 out)
        const __half2* bc2 = (const __half2*)g_w1bc;
        const __half2* dd2 = (const __half2*)g_w1d;
        const float* qb = q + b * D_;
        for (int i2 = tid; i2 < H1_ * 32; i2 += TPB) {   // 5 iters
            const int h = i2 >> 5, dp = i2 & 31;
            float2 bc = __half22float2(bc2[i2]);
            float2 dd = __half22float2(dd2[i2]);
            const float q0 = __ldg(qb + dp * 2), q1 = __ldg(qb + dp * 2 + 1);
            *(__half2*)&sh[MTH + h * KS + dp * 2] =
                __floats2half2_rn(fmaf(q0, dd.x, bc.x), fmaf(q1, dd.y, bc.y));
        }
    }
    __syncthreads();

    // bucket counts (CNT zeroed before barrier above)
    if (tid < T_) atomicAdd(&smi[CNT + smi[CATE + tid]], 1);

    // ---------------- GEMM1 (HMMA + ldmatrix): h1 = PReLU(k @ M + qa) ----------------
    if (warp < 13) {
        const int mt = warp;
        const int r = lane >> 2, qd = lane & 3;
        // A frag addresses: row = mt*16 + (lane&15), col = kk*16 + (lane>=16 ? 8 : 0)
        const uint32_t a_base = sptr(&sh[(mt * 16 + (lane & 15)) * KS + ((lane >> 4) << 3)]);
        // B frag addresses (x4 loads 2 n-groups): row = (p + (lane>>4))*8 + (lane&7),
        // col = kk*16 + ((lane>>3 & 1) ? 8 : 0)
        const uint32_t b1_base = sptr(&sh[MTH + (((lane >> 4) << 3) + (lane & 7)) * KS
                                             + (((lane >> 3) & 1) << 3)]);
#pragma unroll
        for (int hf = 0; hf < 2; ++hf) {
            float acc[5][4];
#pragma unroll
            for (int n5 = 0; n5 < 5; ++n5)
#pragma unroll
                for (int x = 0; x < 4; ++x) acc[n5][x] = 0.f;
#pragma unroll
            for (int kk = 0; kk < 4; ++kk) {
                uint32_t af[4], bf01[4], bf23[4], bf4[2];
                ldm_x4(af, a_base + kk * 32);
                const uint32_t bb = b1_base + (uint32_t)(hf * 5 * 8 * KS * 2) + kk * 32;
                ldm_x4(bf01, bb);
                ldm_x4(bf23, bb + 2u * 8 * KS * 2);
                ldm_x2(bf4,  bb + 4u * 8 * KS * 2);
                mma16816(acc[0], af[0], af[1], af[2], af[3], bf01[0], bf01[1]);
                mma16816(acc[1], af[0], af[1], af[2], af[3], bf01[2], bf01[3]);
                mma16816(acc[2], af[0], af[1], af[2], af[3], bf23[0], bf23[1]);
                mma16816(acc[3], af[0], af[1], af[2], af[3], bf23[2], bf23[3]);
                mma16816(acc[4], af[0], af[1], af[2], af[3], bf4[0],  bf4[1]);
            }
#pragma unroll
            for (int n5 = 0; n5 < 5; ++n5) {
                const int j = (hf * 5 + n5) * 8 + qd * 2;
                const float q0 = sm[QA + j],  q1 = sm[QA + j + 1];
                const float l0 = sm[PA1 + j], l1 = sm[PA1 + j + 1];
                float v0 = acc[n5][0] + q0; v0 = (v0 > 0.f) ? v0 : v0 * l0;
                float v1 = acc[n5][1] + q1; v1 = (v1 > 0.f) ? v1 : v1 * l1;
                float v2 = acc[n5][2] + q0; v2 = (v2 > 0.f) ? v2 : v2 * l0;
                float v3 = acc[n5][3] + q1; v3 = (v3 > 0.f) ? v3 : v3 * l1;
                *(__half2*)&sh[H1H + (mt * 16 + r    ) * HS + j] = __floats2half2_rn(v0, v1);
                *(__half2*)&sh[H1H + (mt * 16 + r + 8) * HS + j] = __floats2half2_rn(v2, v3);
            }
        }
    }
    __syncthreads();

    // ---------------- GEMM2 (HMMA + ldmatrix) + logits; warp15: bucket scan ----------
    if (warp < 13) {
        const int mt = warp;
        const int r = lane >> 2, qd = lane & 3;
        const uint32_t a_base = sptr(&sh[H1H + (mt * 16 + (lane & 15)) * HS
                                            + ((lane >> 4) << 3)]);
        const uint32_t b_base = sptr(&sh[W2H + (((lane >> 4) << 3) + (lane & 7)) * HS
                                            + (((lane >> 3) & 1) << 3)]);
        float acc[5][4];
#pragma unroll
        for (int jn = 0; jn < 5; ++jn)
#pragma unroll
            for (int x = 0; x < 4; ++x) acc[jn][x] = 0.f;
#pragma unroll
        for (int kk = 0; kk < 5; ++kk) {
            uint32_t af[4], bf01[4], bf23[4], bf4[2];
            ldm_x4(af, a_base + kk * 32);
            const uint32_t bb = b_base + kk * 32;
            ldm_x4(bf01, bb);
            ldm_x4(bf23, bb + 2u * 8 * HS * 2);
            ldm_x2(bf4,  bb + 4u * 8 * HS * 2);
            mma16816(acc[0], af[0], af[1], af[2], af[3], bf01[0], bf01[1]);
            mma16816(acc[1], af[0], af[1], af[2], af[3], bf01[2], bf01[3]);
            mma16816(acc[2], af[0], af[1], af[2], af[3], bf23[0], bf23[1]);
            mma16816(acc[3], af[0], af[1], af[2], af[3], bf23[2], bf23[3]);
            mma16816(acc[4], af[0], af[1], af[2], af[3], bf4[0],  bf4[1]);
        }
        float slo = 0.f, shi = 0.f;
#pragma unroll
        for (int jn = 0; jn < 5; ++jn) {
            const int j = jn * 8 + qd * 2;
            const float bb0 = sm[PB2 + j], bb1 = sm[PB2 + j + 1];
            const float al0 = sm[PA2 + j], al1 = sm[PA2 + j + 1];
            const float wf0 = sm[PWF + j], wf1 = sm[PWF + j + 1];
            float x0 = acc[jn][0] + bb0; x0 = (x0 > 0.f) ? x0 : x0 * al0;
            float x1 = acc[jn][1] + bb1; x1 = (x1 > 0.f) ? x1 : x1 * al1;
            float x2 = acc[jn][2] + bb0; x2 = (x2 > 0.f) ? x2 : x2 * al0;
            float x3 = acc[jn][3] + bb1; x3 = (x3 > 0.f) ? x3 : x3 * al1;
            slo += x0 * wf0 + x1 * wf1;
            shi += x2 * wf0 + x3 * wf1;
        }
        slo += __shfl_xor_sync(0xffffffffu, slo, 1);
        slo += __shfl_xor_sync(0xffffffffu, slo, 2);
        shi += __shfl_xor_sync(0xffffffffu, shi, 1);
        shi += __shfl_xor_sync(0xffffffffu, shi, 2);
        if (qd == 0) {
            const float bff = bf[0];
            const int t0 = mt * 16 + r, t1 = t0 + 8;
            if (t0 < T_) {
                float s = slo + bff;
                if (mask[b * T_ + t0] == 0) s = -4294967295.0f;
                sm[WGT + t0] = s * 0.125f;
            }
            if (t1 < T_) {
                float s = shi + bff;
                if (mask[b * T_ + t1] == 0) s = -4294967295.0f;
                sm[WGT + t1] = s * 0.125f;
            }
        }
    }
    if (tid >= 480) {   // warp 15: bucket prefix scan
        const int l = tid - 480;
        const int c0 = smi[CNT + 2 * l], c1 = smi[CNT + 2 * l + 1];
        int s = c0 + c1;
#pragma unroll
        for (int off = 1; off < 32; off <<= 1) {
            int n = __shfl_up_sync(0xffffffffu, s, off);
            if (l >= off) s += n;
        }
        const int excl = s - (c0 + c1);
        smi[BST + 2 * l] = excl;        smi[BST + 2 * l + 1] = excl + c0;
        smi[CNT2 + 2 * l] = excl;       smi[CNT2 + 2 * l + 1] = excl + c0;
    }
    __syncthreads();

    // ---------------- Softmax over 200 ----------------
    {
        float v = (tid < T_) ? sm[WGT + tid] : -3.4e38f;
#pragma unroll
        for (int o = 16; o; o >>= 1) v = fmaxf(v, __shfl_xor_sync(0xffffffffu, v, o));
        if (lane == 0) sm[RED + warp] = v;
        __syncthreads();
        float mx = sm[RED + 0];
#pragma unroll
        for (int i = 1; i < 16; ++i) mx = fmaxf(mx, sm[RED + i]);
        float e = (tid < T_) ? __expf(sm[WGT + tid] - mx) : 0.f;
        float sv = e;
#pragma unroll
        for (int o = 16; o; o >>= 1) sv += __shfl_xor_sync(0xffffffffu, sv, o);
        if (lane == 0) sm[RED + 16 + warp] = sv;
        __syncthreads();
        float S = 0.f;
#pragma unroll
        for (int i = 0; i < 16; ++i) S += sm[RED + 16 + i];
        if (tid < T_) sm[WGT + tid] = e / S;
    }
    __syncthreads();

    // ---------------- Bucket scatter + user_interest partials ----------------
    if (tid < T_) {
        const int c = smi[CATE + tid];
        const int pos = atomicAdd(&smi[CNT2 + c], 1);
        smi[TLIST + pos] = tid;
    }
    {
        const int d = tid & 63, g = tid >> 6;   // 8 groups x 25 t
        float s = 0.f;
        const int tb = g * 25;
#pragma unroll 5
        for (int t = tb; t < tb + 25; ++t)
            s += sm[WGT + t] * __half2float(sh[t * KS + d]);
        sm[PART + tid] = s;
    }
    __syncthreads();

    if (tid < D_) {
        float s = 0.f;
#pragma unroll
        for (int g = 0; g < 8; ++g) s += sm[PART + g * 64 + tid];
        out_ui[b * D_ + tid] = s;
    }

    // ---------------- Bucketed per-category pooling (no atomics) ----------------
    {
        const int g = tid >> 6, d = tid & 63;
        float* ch = out_ch + (size_t)b * C_ * D_;
        for (int c = g; c < C_; c += 8) {
            const int len = smi[CNT + c];
            const int st  = smi[BST + c];
            float acc = 0.f, ws = 0.f;
            for (int i = 0; i < len; ++i) {
                const int t = smi[TLIST + st + i];
                const float w = sm[WGT + t];
                ws  += w;
                acc += w * __half2float(sh[t * KS + d]);
            }
            ch[c * D_ + d] = acc / (ws + 1e-10f);
        }
    }
}

extern "C" void kernel_launch(void* const* d_in, const int* in_sizes, int n_in,
                              void* d_out, int out_size)
{
    const float* q    = (const float*)d_in[0];
    const float* k    = (const float*)d_in[1];
    const int*   mask = (const int*)d_in[2];
    const int*   cate = (const int*)d_in[3];
    // d_in[4] = cate_count (compile-time C_=64)
    const float* W1 = (const float*)d_in[5];
    const float* b1 = (const float*)d_in[6];
    const float* a1 = (const float*)d_in[7];
    const float* W2 = (const float*)d_in[8];
    const float* b2 = (const float*)d_in[9];
    const float* a2 = (const float*)d_in[10];
    const float* Wf = (const float*)d_in[11];
    const float* bf = (const float*)d_in[12];

    const int B = in_sizes[0] / D_;
    float* out_ui = (float*)d_out;                     // [B, 64]
    float* out_ch = (float*)d_out + (size_t)B * D_;    // [B, 64, 64]

    prep_w<<<20, 256>>>(W1, W2);
    prep_qa<<<(B + 15) / 16, 256>>>(q, W1, b1, B);

    cudaFuncSetAttribute(din_kernel, cudaFuncAttributeMaxDynamicSharedMemorySize, SMEM_BYTES);
    din_kernel<<<B, TPB, SMEM_BYTES>>>(q, k, mask, cate, a1, b2, a2, Wf, bf,
                                       out_ui, out_ch);
}

// round 10
// speedup vs baseline: 2.0444x; 1.0690x over previous
#include <cuda_runtime.h>
#include <cuda_fp16.h>
#include <cstdint>

#define TPB 512
#define T_ 200
#define D_ 64
#define H1_ 80
#define H2_ 40
#define C_ 64
#define BMAX 4096

// ---- smem half-index layout ----
#define KH   0            // k fp16 [208][72]   (29,952 B)
#define KS   72
#define MTH  14976        // M^T fp16 [80][72]  (11,520 B)
#define W2H  20736        // W2^T fp16 [40][88] ( 7,040 B)
#define HS   88
// ---- float-index tail (byte 48512) ----
#define QA    12128
#define PA1   12208
#define PB2   12288
#define PA2   12328
#define PWF   12368
#define WGT   12408
#define RED   12608
#define PART  12640
#define CATE  13152
#define CNT   13352
#define CNT2  13416
#define BST   13480
#define TLIST 13544
#define SMEM_FLOATS 13744
#define SMEM_BYTES (SMEM_FLOATS * 4)   // 54,976 B -> 2 CTAs/SM

// ---- device-global prepped weights ----
__device__ __align__(16) __half g_w1bc[H1_ * D_];   // (W1b - W1c)^T  [h][d]
__device__ __align__(16) __half g_w1d [H1_ * D_];   // W1d^T          [h][d]
__device__ __align__(16) __half g_w2t [H2_ * HS];   // W2^T padded    [j][88]
__device__ float g_qa[BMAX * H1_];                  // qa = q@(W1a+W1c)+b1

__device__ __forceinline__ void mma16816(float* c, uint32_t a0, uint32_t a1,
                                         uint32_t a2, uint32_t a3,
                                         uint32_t b0, uint32_t b1) {
    asm volatile(
        "mma.sync.aligned.m16n8k16.row.col.f32.f16.f16.f32 "
        "{%0,%1,%2,%3}, {%4,%5,%6,%7}, {%8,%9}, {%0,%1,%2,%3};"
        : "+f"(c[0]), "+f"(c[1]), "+f"(c[2]), "+f"(c[3])
        : "r"(a0), "r"(a1), "r"(a2), "r"(a3), "r"(b0), "r"(b1));
}
__device__ __forceinline__ void ldm_x4(uint32_t* r, uint32_t addr) {
    asm volatile("ldmatrix.sync.aligned.m8n8.x4.shared.b16 {%0,%1,%2,%3}, [%4];"
        : "=r"(r[0]), "=r"(r[1]), "=r"(r[2]), "=r"(r[3]) : "r"(addr));
}
__device__ __forceinline__ void ldm_x2(uint32_t* r, uint32_t addr) {
    asm volatile("ldmatrix.sync.aligned.m8n8.x2.shared.b16 {%0,%1}, [%2];"
        : "=r"(r[0]), "=r"(r[1]) : "r"(addr));
}
__device__ __forceinline__ uint32_t sptr(const void* p) {
    return (uint32_t)__cvta_generic_to_shared(p);
}
__device__ __forceinline__ uint32_t packh2(float a, float b) {
    __half2 h = __floats2half2_rn(a, b);
    return *(uint32_t*)&h;
}

// ---------- merged prep kernel (block 0: weights; blocks 1..: qa) ----------
__global__ void prep_all(const float* __restrict__ q, const float* __restrict__ W1,
                         const float* __restrict__ b1, const float* __restrict__ W2,
                         int B) {
    const int tid = threadIdx.x;
    if (blockIdx.x == 0) {
        for (int i = tid; i < H1_ * D_; i += 256) {
            const int h = i >> 6, d = i & 63;
            g_w1bc[i] = __float2half_rn(W1[(64 + d) * H1_ + h] - W1[(128 + d) * H1_ + h]);
            g_w1d[i]  = __float2half_rn(W1[(192 + d) * H1_ + h]);
        }
        for (int i = tid; i < H2_ * HS; i += 256) {
            const int j = i / HS, c = i - j * HS;
            g_w2t[i] = (c < H1_) ? __float2half_rn(W2[c * H2_ + j]) : __float2half_rn(0.f);
        }
        return;
    }
    __shared__ float ws[D_ * H1_];
    for (int i = tid; i < D_ * H1_; i += 256) {
        const int d = i / H1_, h = i - d * H1_;
        ws[i] = W1[d * H1_ + h] + W1[(128 + d) * H1_ + h];
    }
    __syncthreads();
    const int b0 = (blockIdx.x - 1) * 16;
    for (int o = tid; o < 16 * H1_; o += 256) {
        const int bb = b0 + o / H1_, h = o % H1_;
        if (bb < B) {
            float s = b1[h];
            const float* qr = q + bb * D_;
#pragma unroll 8
            for (int d = 0; d < D_; ++d) s += qr[d] * ws[d * H1_ + h];
            g_qa[bb * H1_ + h] = s;
        }
    }
}

// ---------------------------- main kernel ----------------------------
__global__ __launch_bounds__(TPB, 2)
void din_kernel(const float* __restrict__ q, const float* __restrict__ k,
                const int* __restrict__ mask, const int* __restrict__ cate,
                const float* __restrict__ a1, const float* __restrict__ b2,
                const float* __restrict__ a2, const float* __restrict__ Wf,
                const float* __restrict__ bf,
                float* __restrict__ out_ui, float* __restrict__ out_ch)
{
    extern __shared__ float sm[];
    int* smi = (int*)sm;
    __half* sh = (__half*)sm;
    const int b = blockIdx.x;
    const int tid = threadIdx.x;
    const int lane = tid & 31, warp = tid >> 5;

    // ---------------- Phase 0: params, k->fp16, W2^T, M^T ----------------
    if (tid < H1_) { sm[QA + tid] = g_qa[b * H1_ + tid]; sm[PA1 + tid] = a1[tid]; }
    if (tid < H2_) { sm[PB2 + tid] = b2[tid]; sm[PA2 + tid] = a2[tid]; sm[PWF + tid] = Wf[tid]; }
    if (tid < T_)  smi[CATE + tid] = cate[b * T_ + tid];
    if (tid < C_)  smi[CNT + tid] = 0;
    {   // k -> fp16 [208][72]
        const float4* k4 = (const float4*)(k + (size_t)b * T_ * D_);
        for (int idx = tid; idx < T_ * 16; idx += TPB) {
            float4 v = k4[idx];
            const int t = idx >> 4, f4 = idx & 15;
            uint2 u;
            *(__half2*)&u.x = __floats2half2_rn(v.x, v.y);
            *(__half2*)&u.y = __floats2half2_rn(v.z, v.w);
            *(uint2*)&sh[t * KS + f4 * 4] = u;
        }
        if (tid < 128) {                       // zero-pad rows 200..207
            const int t = 200 + (tid >> 4), d4 = (tid & 15) * 4;
            *(uint2*)&sh[t * KS + d4] = make_uint2(0u, 0u);
        }
    }
    {   // W2^T pre-padded copy: 440 uint4
        const uint4* w2g = (const uint4*)g_w2t;
        uint4* w2s = (uint4*)&sh[W2H];
        if (tid < 440) w2s[tid] = w2g[tid];
    }
    {   // M^T[h][d] = w1bc + q_d * w1d
        const __half2* bc2 = (const __half2*)g_w1bc;
        const __half2* dd2 = (const __half2*)g_w1d;
        const float* qb = q + b * D_;
        for (int i2 = tid; i2 < H1_ * 32; i2 += TPB) {   // 5 iters
            const int h = i2 >> 5, dp = i2 & 31;
            float2 bc = __half22float2(bc2[i2]);
            float2 dd = __half22float2(dd2[i2]);
            const float q0 = __ldg(qb + dp * 2), q1 = __ldg(qb + dp * 2 + 1);
            *(__half2*)&sh[MTH + h * KS + dp * 2] =
                __floats2half2_rn(fmaf(q0, dd.x, bc.x), fmaf(q1, dd.y, bc.y));
        }
    }
    __syncthreads();

    // bucket counts (completes before the post-GEMM barrier; scan runs after it)
    if (tid < T_) atomicAdd(&smi[CNT + smi[CATE + tid]], 1);

    // ------- Fused GEMM1 -> PReLU -> GEMM2 -> logits (register-resident) -------
    if (warp < 13) {
        const int mt = warp;
        const int r = lane >> 2, qd = lane & 3;
        const uint32_t a_base  = sptr(&sh[(mt * 16 + (lane & 15)) * KS + ((lane >> 4) << 3)]);
        const uint32_t b1_base = sptr(&sh[MTH + (((lane >> 4) << 3) + (lane & 7)) * KS
                                              + (((lane >> 3) & 1) << 3)]);
        const uint32_t b2_base = sptr(&sh[W2H + (((lane >> 4) << 3) + (lane & 7)) * HS
                                              + (((lane >> 3) & 1) << 3)]);
        float acc2[5][4];
#pragma unroll
        for (int jn = 0; jn < 5; ++jn)
#pragma unroll
            for (int x = 0; x < 4; ++x) acc2[jn][x] = 0.f;

#pragma unroll
        for (int np = 0; np < 5; ++np) {            // 16 h1-cols per chunk
            float alo[4] = {0.f, 0.f, 0.f, 0.f};
            float ahi[4] = {0.f, 0.f, 0.f, 0.f};
#pragma unroll
            for (int kk = 0; kk < 4; ++kk) {
                uint32_t af[4], bp[4];
                ldm_x4(af, a_base + kk * 32);
                ldm_x4(bp, b1_base + (uint32_t)(np * 16 * KS * 2) + kk * 32);
                mma16816(alo, af[0], af[1], af[2], af[3], bp[0], bp[1]);
                mma16816(ahi, af[0], af[1], af[2], af[3], bp[2], bp[3]);
            }
            // epilogue: +qa, PReLU, pack straight into GEMM2 A-fragment
            const int jl = np * 16 + qd * 2, jh = jl + 8;
            const float ql0 = sm[QA + jl],  ql1 = sm[QA + jl + 1];
            const float ll0 = sm[PA1 + jl], ll1 = sm[PA1 + jl + 1];
            const float qh0 = sm[QA + jh],  qh1 = sm[QA + jh + 1];
            const float lh0 = sm[PA1 + jh], lh1 = sm[PA1 + jh + 1];
            float v0 = alo[0] + ql0; v0 = (v0 > 0.f) ? v0 : v0 * ll0;
            float v1 = alo[1] + ql1; v1 = (v1 > 0.f) ? v1 : v1 * ll1;
            float v2 = alo[2] + ql0; v2 = (v2 > 0.f) ? v2 : v2 * ll0;
            float v3 = alo[3] + ql1; v3 = (v3 > 0.f) ? v3 : v3 * ll1;
            float w0 = ahi[0] + qh0; w0 = (w0 > 0.f) ? w0 : w0 * lh0;
            float w1 = ahi[1] + qh1; w1 = (w1 > 0.f) ? w1 : w1 * lh1;
            float w2 = ahi[2] + qh0; w2 = (w2 > 0.f) ? w2 : w2 * lh0;
            float w3 = ahi[3] + qh1; w3 = (w3 > 0.f) ? w3 : w3 * lh1;
            const uint32_t A0 = packh2(v0, v1);   // (row r,   cols jl)
            const uint32_t A1 = packh2(v2, v3);   // (row r+8, cols jl)
            const uint32_t A2 = packh2(w0, w1);   // (row r,   cols jh)
            const uint32_t A3 = packh2(w2, w3);   // (row r+8, cols jh)
            // GEMM2 k-chunk np
            uint32_t b01[4], b23[4], b4[2];
            const uint32_t bb = b2_base + np * 32;
            ldm_x4(b01, bb);
            ldm_x4(b23, bb + 2u * 8 * HS * 2);
            ldm_x2(b4,  bb + 4u * 8 * HS * 2);
            mma16816(acc2[0], A0, A1, A2, A3, b01[0], b01[1]);
            mma16816(acc2[1], A0, A1, A2, A3, b01[2], b01[3]);
            mma16816(acc2[2], A0, A1, A2, A3, b23[0], b23[1]);
            mma16816(acc2[3], A0, A1, A2, A3, b23[2], b23[3]);
            mma16816(acc2[4], A0, A1, A2, A3, b4[0],  b4[1]);
        }
        // logits epilogue
        float slo = 0.f, shi = 0.f;
#pragma unroll
        for (int jn = 0; jn < 5; ++jn) {
            const int j = jn * 8 + qd * 2;
            const float bb0 = sm[PB2 + j], bb1 = sm[PB2 + j + 1];
            const float al0 = sm[PA2 + j], al1 = sm[PA2 + j + 1];
            const float wf0 = sm[PWF + j], wf1 = sm[PWF + j + 1];
            float x0 = acc2[jn][0] + bb0; x0 = (x0 > 0.f) ? x0 : x0 * al0;
            float x1 = acc2[jn][1] + bb1; x1 = (x1 > 0.f) ? x1 : x1 * al1;
            float x2 = acc2[jn][2] + bb0; x2 = (x2 > 0.f) ? x2 : x2 * al0;
            float x3 = acc2[jn][3] + bb1; x3 = (x3 > 0.f) ? x3 : x3 * al1;
            slo += x0 * wf0 + x1 * wf1;
            shi += x2 * wf0 + x3 * wf1;
        }
        slo += __shfl_xor_sync(0xffffffffu, slo, 1);
        slo += __shfl_xor_sync(0xffffffffu, slo, 2);
        shi += __shfl_xor_sync(0xffffffffu, shi, 1);
        shi += __shfl_xor_sync(0xffffffffu, shi, 2);
        if (qd == 0) {
            const float bff = bf[0];
            const int t0 = mt * 16 + r, t1 = t0 + 8;
            if (t0 < T_) {
                float s = slo + bff;
                if (mask[b * T_ + t0] == 0) s = -4294967295.0f;
                sm[WGT + t0] = s * 0.125f;
            }
            if (t1 < T_) {
                float s = shi + bff;
                if (mask[b * T_ + t1] == 0) s = -4294967295.0f;
                sm[WGT + t1] = s * 0.125f;
            }
        }
    }
    __syncthreads();   // logits + CNT final

    // ---------------- Softmax over 200 (warp15: bucket scan, post-barrier) ----------
    {
        if (tid >= 480) {   // CNT atomicAdds all completed before the barrier above
            const int l = tid - 480;
            const int c0 = smi[CNT + 2 * l], c1 = smi[CNT + 2 * l + 1];
            int s = c0 + c1;
#pragma unroll
            for (int off = 1; off < 32; off <<= 1) {
                int n = __shfl_up_sync(0xffffffffu, s, off);
                if (l >= off) s += n;
            }
            const int excl = s - (c0 + c1);
            smi[BST + 2 * l] = excl;        smi[BST + 2 * l + 1] = excl + c0;
            smi[CNT2 + 2 * l] = excl;       smi[CNT2 + 2 * l + 1] = excl + c0;
        }
        float v = (tid < T_) ? sm[WGT + tid] : -3.4e38f;
#pragma unroll
        for (int o = 16; o; o >>= 1) v = fmaxf(v, __shfl_xor_sync(0xffffffffu, v, o));
        if (lane == 0) sm[RED + warp] = v;
        __syncthreads();
        float mx = sm[RED + 0];
#pragma unroll
        for (int i = 1; i < 16; ++i) mx = fmaxf(mx, sm[RED + i]);
        float e = (tid < T_) ? __expf(sm[WGT + tid] - mx) : 0.f;
        float sv = e;
#pragma unroll
        for (int o = 16; o; o >>= 1) sv += __shfl_xor_sync(0xffffffffu, sv, o);
        if (lane == 0) sm[RED + 16 + warp] = sv;
        __syncthreads();
        float S = 0.f;
#pragma unroll
        for (int i = 0; i < 16; ++i) S += sm[RED + 16 + i];
        if (tid < T_) sm[WGT + tid] = e / S;
    }
    __syncthreads();

    // ---------------- Bucket scatter + user_interest partials ----------------
    if (tid < T_) {
        const int c = smi[CATE + tid];
        const int pos = atomicAdd(&smi[CNT2 + c], 1);
        smi[TLIST + pos] = tid;
    }
    {
        const int d = tid & 63, g = tid >> 6;   // 8 groups x 25 t
        float s = 0.f;
        const int tb = g * 25;
#pragma unroll 5
        for (int t = tb; t < tb + 25; ++t)
            s += sm[WGT + t] * __half2float(sh[t * KS + d]);
        sm[PART + tid] = s;
    }
    __syncthreads();

    if (tid < D_) {
        float s = 0.f;
#pragma unroll
        for (int g = 0; g < 8; ++g) s += sm[PART + g * 64 + tid];
        out_ui[b * D_ + tid] = s;
    }

    // ---------------- Bucketed per-category pooling (no atomics) ----------------
    {
        const int g = tid >> 6, d = tid & 63;
        float* ch = out_ch + (size_t)b * C_ * D_;
        for (int c = g; c < C_; c += 8) {
            const int len = smi[CNT + c];
            const int st  = smi[BST + c];
            float acc = 0.f, ws = 0.f;
            for (int i = 0; i < len; ++i) {
                const int t = smi[TLIST + st + i];
                const float w = sm[WGT + t];
                ws  += w;
                acc += w * __half2float(sh[t * KS + d]);
            }
            ch[c * D_ + d] = acc / (ws + 1e-10f);
        }
    }
}

extern "C" void kernel_launch(void* const* d_in, const int* in_sizes, int n_in,
                              void* d_out, int out_size)
{
    const float* q    = (const float*)d_in[0];
    const float* k    = (const float*)d_in[1];
    const int*   mask = (const int*)d_in[2];
    const int*   cate = (const int*)d_in[3];
    // d_in[4] = cate_count (compile-time C_=64)
    const float* W1 = (const float*)d_in[5];
    const float* b1 = (const float*)d_in[6];
    const float* a1 = (const float*)d_in[7];
    const float* W2 = (const float*)d_in[8];
    const float* b2 = (const float*)d_in[9];
    const float* a2 = (const float*)d_in[10];
    const float* Wf = (const float*)d_in[11];
    const float* bf = (const float*)d_in[12];

    const int B = in_sizes[0] / D_;
    float* out_ui = (float*)d_out;                     // [B, 64]
    float* out_ch = (float*)d_out + (size_t)B * D_;    // [B, 64, 64]

    prep_all<<<1 + (B + 15) / 16, 256>>>(q, W1, b1, W2, B);

    cudaFuncSetAttribute(din_kernel, cudaFuncAttributeMaxDynamicSharedMemorySize, SMEM_BYTES);
    din_kernel<<<B, TPB, SMEM_BYTES>>>(q, k, mask, cate, a1, b2, a2, Wf, bf,
                                       out_ui, out_ch);
}

// round 11
// speedup vs baseline: 2.1415x; 1.0475x over previous
#include <cuda_runtime.h>
#include <cuda_fp16.h>
#include <cstdint>

#define TPB 512
#define T_ 200
#define D_ 64
#define H1_ 80
#define H2_ 40
#define C_ 64

// ---- smem half-index layout ----
#define KH   0            // k fp16 [208][72]; cols 64-71: {1,0,...} ones-column pad
#define KS   72
#define MTH  14976        // M^T fp16 [80][72]
#define W2H  20736        // W2^T fp16 [40][88]
#define HS   88
#define WCH  27488        // Wc fp16 [64][216] scattered softmax weights (byte 54976)
#define WCS  216
// ---- float-index regions ----
#define CHF   7488        // CH f32 [64][72] cate numerators (aliases MTH/W2H, post-GEMM)
#define CHS   72
#define QA    12128
#define PA1   12208
#define PB2   12288
#define PA2   12328
#define PWF   12368
#define WGT   12408
#define RED   12608
#define PART  12640       // [512]
#define WSF   13152       // WS f32 [64]
#define SMEM_BYTES 82624  // -> 2 CTAs/SM

// ---- device-global prepped weights ----
__device__ __align__(16) __half g_w1bc[H1_ * D_];   // (W1b - W1c)^T  [h][d]
__device__ __align__(16) __half g_w1d [H1_ * D_];   // W1d^T          [h][d]
__device__ __align__(16) __half g_w1ac[H1_ * D_];   // (W1a + W1c)^T  [h][d]
__device__ __align__(16) __half g_w2t [H2_ * HS];   // W2^T padded    [j][88]

__device__ __forceinline__ void mma16816(float* c, uint32_t a0, uint32_t a1,
                                         uint32_t a2, uint32_t a3,
                                         uint32_t b0, uint32_t b1) {
    asm volatile(
        "mma.sync.aligned.m16n8k16.row.col.f32.f16.f16.f32 "
        "{%0,%1,%2,%3}, {%4,%5,%6,%7}, {%8,%9}, {%0,%1,%2,%3};"
        : "+f"(c[0]), "+f"(c[1]), "+f"(c[2]), "+f"(c[3])
        : "r"(a0), "r"(a1), "r"(a2), "r"(a3), "r"(b0), "r"(b1));
}
__device__ __forceinline__ void ldm_x4(uint32_t* r, uint32_t addr) {
    asm volatile("ldmatrix.sync.aligned.m8n8.x4.shared.b16 {%0,%1,%2,%3}, [%4];"
        : "=r"(r[0]), "=r"(r[1]), "=r"(r[2]), "=r"(r[3]) : "r"(addr));
}
__device__ __forceinline__ void ldm_x2(uint32_t* r, uint32_t addr) {
    asm volatile("ldmatrix.sync.aligned.m8n8.x2.shared.b16 {%0,%1}, [%2];"
        : "=r"(r[0]), "=r"(r[1]) : "r"(addr));
}
__device__ __forceinline__ void ldm_x4t(uint32_t* r, uint32_t addr) {
    asm volatile("ldmatrix.sync.aligned.m8n8.x4.trans.shared.b16 {%0,%1,%2,%3}, [%4];"
        : "=r"(r[0]), "=r"(r[1]), "=r"(r[2]), "=r"(r[3]) : "r"(addr));
}
__device__ __forceinline__ void ldm_x2t(uint32_t* r, uint32_t addr) {
    asm volatile("ldmatrix.sync.aligned.m8n8.x2.trans.shared.b16 {%0,%1}, [%2];"
        : "=r"(r[0]), "=r"(r[1]) : "r"(addr));
}
__device__ __forceinline__ uint32_t sptr(const void* p) {
    return (uint32_t)__cvta_generic_to_shared(p);
}
__device__ __forceinline__ uint32_t packh2(float a, float b) {
    __half2 h = __floats2half2_rn(a, b);
    return *(uint32_t*)&h;
}

// ---------- prep kernel: batch-invariant weight transforms only ----------
__global__ void prep_w(const float* __restrict__ W1, const float* __restrict__ W2) {
    const int g = blockIdx.x * blockDim.x + threadIdx.x;
    const int stride = gridDim.x * blockDim.x;
    for (int i = g; i < H1_ * D_; i += stride) {
        const int h = i >> 6, d = i & 63;
        g_w1bc[i] = __float2half_rn(W1[(64 + d) * H1_ + h] - W1[(128 + d) * H1_ + h]);
        g_w1d[i]  = __float2half_rn(W1[(192 + d) * H1_ + h]);
        g_w1ac[i] = __float2half_rn(W1[d * H1_ + h] + W1[(128 + d) * H1_ + h]);
    }
    for (int i = g; i < H2_ * HS; i += stride) {
        const int j = i / HS, c = i - j * HS;
        g_w2t[i] = (c < H1_) ? __float2half_rn(W2[c * H2_ + j]) : __float2half_rn(0.f);
    }
}

// ---------------------------- main kernel ----------------------------
__global__ __launch_bounds__(TPB, 2)
void din_kernel(const float* __restrict__ q, const float* __restrict__ k,
                const int* __restrict__ mask, const int* __restrict__ cate,
                const float* __restrict__ b1, const float* __restrict__ a1,
                const float* __restrict__ b2, const float* __restrict__ a2,
                const float* __restrict__ Wf, const float* __restrict__ bf,
                float* __restrict__ out_ui, float* __restrict__ out_ch)
{
    extern __shared__ float sm[];
    __half* sh = (__half*)sm;
    const int b = blockIdx.x;
    const int tid = threadIdx.x;
    const int lane = tid & 31, warp = tid >> 5;
    const float* qb = q + b * D_;

    // ---------------- Phase 0: params, k->fp16, W2^T, M^T, qa, zero Wc ---------------
    if (tid < H1_) sm[PA1 + tid] = a1[tid];
    if (tid < H2_) { sm[PB2 + tid] = b2[tid]; sm[PA2 + tid] = a2[tid]; sm[PWF + tid] = Wf[tid]; }
    {   // k -> fp16 [208][72]
        const float4* k4 = (const float4*)(k + (size_t)b * T_ * D_);
        for (int idx = tid; idx < T_ * 16; idx += TPB) {
            float4 v = k4[idx];
            const int t = idx >> 4, f4 = idx & 15;
            uint2 u;
            *(__half2*)&u.x = __floats2half2_rn(v.x, v.y);
            *(__half2*)&u.y = __floats2half2_rn(v.z, v.w);
            *(uint2*)&sh[t * KS + f4 * 4] = u;
        }
        if (tid < 128) {                       // zero rows 200..207, cols 0..63
            const int t = 200 + (tid >> 4), d4 = (tid & 15) * 4;
            *(uint2*)&sh[t * KS + d4] = make_uint2(0u, 0u);
        }
        if (tid < 208)                         // ones-column pad: col64=1.0, 65-71=0
            *(uint4*)&sh[tid * KS + 64] = make_uint4(0x00003C00u, 0u, 0u, 0u);
    }
    {   // zero Wc [64][216] fp16
        uint4* wc4 = (uint4*)&sh[WCH];
        for (int i = tid; i < (C_ * WCS) / 8; i += TPB) wc4[i] = make_uint4(0u, 0u, 0u, 0u);
    }
    {   // W2^T pre-padded copy
        const uint4* w2g = (const uint4*)g_w2t;
        uint4* w2s = (uint4*)&sh[W2H];
        if (tid < 440) w2s[tid] = w2g[tid];
    }
    {   // M^T[h][d] = w1bc + q_d * w1d
        const __half2* bc2 = (const __half2*)g_w1bc;
        const __half2* dd2 = (const __half2*)g_w1d;
        for (int i2 = tid; i2 < H1_ * 32; i2 += TPB) {
            const int h = i2 >> 5, dp = i2 & 31;
            float2 bc = __half22float2(bc2[i2]);
            float2 dd = __half22float2(dd2[i2]);
            const float q0 = __ldg(qb + dp * 2), q1 = __ldg(qb + dp * 2 + 1);
            *(__half2*)&sh[MTH + h * KS + dp * 2] =
                __floats2half2_rn(fmaf(q0, dd.x, bc.x), fmaf(q1, dd.y, bc.y));
        }
    }
    if (tid < 320) {   // qa[h] = b1[h] + q . w1ac[h]
        const int h = tid >> 2, qq = tid & 3;
        const __half2* ac2 = (const __half2*)(g_w1ac + h * 64 + qq * 16);
        float s = 0.f;
#pragma unroll
        for (int p = 0; p < 8; ++p) {
            float2 f = __half22float2(ac2[p]);
            s += __ldg(qb + qq * 16 + 2 * p) * f.x + __ldg(qb + qq * 16 + 2 * p + 1) * f.y;
        }
        s += __shfl_xor_sync(0xffffffffu, s, 1);
        s += __shfl_xor_sync(0xffffffffu, s, 2);
        if (qq == 0) sm[QA + h] = s + b1[h];
    }
    __syncthreads();

    // ------- Fused GEMM1 -> PReLU -> GEMM2 -> logits (register-resident) -------
    if (warp < 13) {
        const int mt = warp;
        const int r = lane >> 2, qd = lane & 3;
        const uint32_t a_base  = sptr(&sh[(mt * 16 + (lane & 15)) * KS + ((lane >> 4) << 3)]);
        const uint32_t b1_base = sptr(&sh[MTH + (((lane >> 4) << 3) + (lane & 7)) * KS
                                              + (((lane >> 3) & 1) << 3)]);
        const uint32_t b2_base = sptr(&sh[W2H + (((lane >> 4) << 3) + (lane & 7)) * HS
                                              + (((lane >> 3) & 1) << 3)]);
        float acc2[5][4];
#pragma unroll
        for (int jn = 0; jn < 5; ++jn)
#pragma unroll
            for (int x = 0; x < 4; ++x) acc2[jn][x] = 0.f;

#pragma unroll
        for (int np = 0; np < 5; ++np) {
            float alo[4] = {0.f, 0.f, 0.f, 0.f};
            float ahi[4] = {0.f, 0.f, 0.f, 0.f};
#pragma unroll
            for (int kk = 0; kk < 4; ++kk) {
                uint32_t af[4], bp[4];
                ldm_x4(af, a_base + kk * 32);
                ldm_x4(bp, b1_base + (uint32_t)(np * 16 * KS * 2) + kk * 32);
                mma16816(alo, af[0], af[1], af[2], af[3], bp[0], bp[1]);
                mma16816(ahi, af[0], af[1], af[2], af[3], bp[2], bp[3]);
            }
            const int jl = np * 16 + qd * 2, jh = jl + 8;
            const float ql0 = sm[QA + jl],  ql1 = sm[QA + jl + 1];
            const float ll0 = sm[PA1 + jl], ll1 = sm[PA1 + jl + 1];
            const float qh0 = sm[QA + jh],  qh1 = sm[QA + jh + 1];
            const float lh0 = sm[PA1 + jh], lh1 = sm[PA1 + jh + 1];
            float v0 = alo[0] + ql0; v0 = (v0 > 0.f) ? v0 : v0 * ll0;
            float v1 = alo[1] + ql1; v1 = (v1 > 0.f) ? v1 : v1 * ll1;
            float v2 = alo[2] + ql0; v2 = (v2 > 0.f) ? v2 : v2 * ll0;
            float v3 = alo[3] + ql1; v3 = (v3 > 0.f) ? v3 : v3 * ll1;
            float w0 = ahi[0] + qh0; w0 = (w0 > 0.f) ? w0 : w0 * lh0;
            float w1 = ahi[1] + qh1; w1 = (w1 > 0.f) ? w1 : w1 * lh1;
            float w2 = ahi[2] + qh0; w2 = (w2 > 0.f) ? w2 : w2 * lh0;
            float w3 = ahi[3] + qh1; w3 = (w3 > 0.f) ? w3 : w3 * lh1;
            const uint32_t A0 = packh2(v0, v1);
            const uint32_t A1 = packh2(v2, v3);
            const uint32_t A2 = packh2(w0, w1);
            const uint32_t A3 = packh2(w2, w3);
            uint32_t b01[4], b23[4], b4[2];
            const uint32_t bb = b2_base + np * 32;
            ldm_x4(b01, bb);
            ldm_x4(b23, bb + 2u * 8 * HS * 2);
            ldm_x2(b4,  bb + 4u * 8 * HS * 2);
            mma16816(acc2[0], A0, A1, A2, A3, b01[0], b01[1]);
            mma16816(acc2[1], A0, A1, A2, A3, b01[2], b01[3]);
            mma16816(acc2[2], A0, A1, A2, A3, b23[0], b23[1]);
            mma16816(acc2[3], A0, A1, A2, A3, b23[2], b23[3]);
            mma16816(acc2[4], A0, A1, A2, A3, b4[0],  b4[1]);
        }
        float slo = 0.f, shi = 0.f;
#pragma unroll
        for (int jn = 0; jn < 5; ++jn) {
            const int j = jn * 8 + qd * 2;
            const float bb0 = sm[PB2 + j], bb1 = sm[PB2 + j + 1];
            const float al0 = sm[PA2 + j], al1 = sm[PA2 + j + 1];
            const float wf0 = sm[PWF + j], wf1 = sm[PWF + j + 1];
            float x0 = acc2[jn][0] + bb0; x0 = (x0 > 0.f) ? x0 : x0 * al0;
            float x1 = acc2[jn][1] + bb1; x1 = (x1 > 0.f) ? x1 : x1 * al1;
            float x2 = acc2[jn][2] + bb0; x2 = (x2 > 0.f) ? x2 : x2 * al0;
            float x3 = acc2[jn][3] + bb1; x3 = (x3 > 0.f) ? x3 : x3 * al1;
            slo += x0 * wf0 + x1 * wf1;
            shi += x2 * wf0 + x3 * wf1;
        }
        slo += __shfl_xor_sync(0xffffffffu, slo, 1);
        slo += __shfl_xor_sync(0xffffffffu, slo, 2);
        shi += __shfl_xor_sync(0xffffffffu, shi, 1);
        shi += __shfl_xor_sync(0xffffffffu, shi, 2);
        if (qd == 0) {
            const float bff = bf[0];
            const int t0 = mt * 16 + r, t1 = t0 + 8;
            if (t0 < T_) {
                float s = slo + bff;
                if (mask[b * T_ + t0] == 0) s = -4294967295.0f;
                sm[WGT + t0] = s * 0.125f;
            }
            if (t1 < T_) {
                float s = shi + bff;
                if (mask[b * T_ + t1] == 0) s = -4294967295.0f;
                sm[WGT + t1] = s * 0.125f;
            }
        }
    }
    __syncthreads();

    // ---------------- Softmax over 200 + scatter w into Wc ----------------
    {
        float v = (tid < T_) ? sm[WGT + tid] : -3.4e38f;
#pragma unroll
        for (int o = 16; o; o >>= 1) v = fmaxf(v, __shfl_xor_sync(0xffffffffu, v, o));
        if (lane == 0) sm[RED + warp] = v;
        __syncthreads();
        float mx = sm[RED + 0];
#pragma unroll
        for (int i = 1; i < 16; ++i) mx = fmaxf(mx, sm[RED + i]);
        float e = (tid < T_) ? __expf(sm[WGT + tid] - mx) : 0.f;
        float sv = e;
#pragma unroll
        for (int o = 16; o; o >>= 1) sv += __shfl_xor_sync(0xffffffffu, sv, o);
        if (lane == 0) sm[RED + 16 + warp] = sv;
        __syncthreads();
        float S = 0.f;
#pragma unroll
        for (int i = 0; i < 16; ++i) S += sm[RED + 16 + i];
        if (tid < T_) {
            const float w = e / S;
            sm[WGT + tid] = w;
            const int ct = cate[b * T_ + tid];
            sh[WCH + ct * WCS + tid] = __float2half_rn(w);
        }
    }
    __syncthreads();

    // ---------------- user_interest partials (fp32 w, fp16 k) ----------------
    {
        const int d = tid & 63, g = tid >> 6;
        float s = 0.f;
        const int tb = g * 25;
#pragma unroll 5
        for (int t = tb; t < tb + 25; ++t)
            s += sm[WGT + t] * __half2float(sh[t * KS + d]);
        sm[PART + tid] = s;
    }
    __syncthreads();

    // ------- Cate GEMM (HMMA): CH = Wc @ k  (N=72, col 64 = ws); warp12: ui -------
    if (warp < 12) {
        const int mt = warp & 3, g = warp >> 2;
        const int r = lane >> 2, qd = lane & 3;
        const int n0 = g * 24;
        const uint32_t aw_base = sptr(&sh[WCH + (mt * 16 + (lane & 15)) * WCS
                                              + ((lane >> 4) << 3)]);
        const int krow = (lane & 7) + ((lane >> 3) & 1) * 8;
        const uint32_t bt4_base = sptr(&sh[krow * KS + n0 + ((lane >> 4) << 3)]);
        const uint32_t bt2_base = sptr(&sh[krow * KS + n0 + 16]);
        float acc[3][4];
#pragma unroll
        for (int j = 0; j < 3; ++j)
#pragma unroll
            for (int x = 0; x < 4; ++x) acc[j][x] = 0.f;
#pragma unroll
        for (int kc = 0; kc < 13; ++kc) {
            uint32_t af[4], bt[4], b2r[2];
            ldm_x4 (af,  aw_base  + kc * 32);
            ldm_x4t(bt,  bt4_base + (uint32_t)(kc * 16 * KS * 2));
            ldm_x2t(b2r, bt2_base + (uint32_t)(kc * 16 * KS * 2));
            mma16816(acc[0], af[0], af[1], af[2], af[3], bt[0], bt[1]);
            mma16816(acc[1], af[0], af[1], af[2], af[3], bt[2], bt[3]);
            mma16816(acc[2], af[0], af[1], af[2], af[3], b2r[0], b2r[1]);
        }
        const int c0 = mt * 16 + r;
#pragma unroll
        for (int j = 0; j < 3; ++j) {
            const int col = n0 + j * 8 + qd * 2;
            if (col < 64) {
                sm[CHF + c0 * CHS + col]           = acc[j][0];
                sm[CHF + c0 * CHS + col + 1]       = acc[j][1];
                sm[CHF + (c0 + 8) * CHS + col]     = acc[j][2];
                sm[CHF + (c0 + 8) * CHS + col + 1] = acc[j][3];
            } else if (col == 64) {
                sm[WSF + c0]     = acc[j][0];
                sm[WSF + c0 + 8] = acc[j][2];
            }
        }
    } else if (warp == 12) {
#pragma unroll
        for (int d = lane; d < D_; d += 32) {
            float s = 0.f;
#pragma unroll
            for (int g = 0; g < 8; ++g) s += sm[PART + g * 64 + d];
            out_ui[b * D_ + d] = s;
        }
    }
    __syncthreads();

    // ---------------- Normalize + store cate_hidden ----------------
    {
        float* ch = out_ch + (size_t)b * C_ * D_;
#pragma unroll
        for (int i = tid; i < C_ * D_; i += TPB) {
            const int c = i >> 6, d = i & 63;
            ch[i] = sm[CHF + c * CHS + d] / (sm[WSF + c] + 1e-10f);
        }
    }
}

extern "C" void kernel_launch(void* const* d_in, const int* in_sizes, int n_in,
                              void* d_out, int out_size)
{
    const float* q    = (const float*)d_in[0];
    const float* k    = (const float*)d_in[1];
    const int*   mask = (const int*)d_in[2];
    const int*   cate = (const int*)d_in[3];
    // d_in[4] = cate_count (compile-time C_=64)
    const float* W1 = (const float*)d_in[5];
    const float* b1 = (const float*)d_in[6];
    const float* a1 = (const float*)d_in[7];
    const float* W2 = (const float*)d_in[8];
    const float* b2 = (const float*)d_in[9];
    const float* a2 = (const float*)d_in[10];
    const float* Wf = (const float*)d_in[11];
    const float* bf = (const float*)d_in[12];

    const int B = in_sizes[0] / D_;
    float* out_ui = (float*)d_out;                     // [B, 64]
    float* out_ch = (float*)d_out + (size_t)B * D_;    // [B, 64, 64]

    prep_w<<<8, 256>>>(W1, W2);

    cudaFuncSetAttribute(din_kernel, cudaFuncAttributeMaxDynamicSharedMemorySize, SMEM_BYTES);
    din_kernel<<<B, TPB, SMEM_BYTES>>>(q, k, mask, cate, b1, a1, b2, a2, Wf, bf,
                                       out_ui, out_ch);
}

// round 12
// speedup vs baseline: 2.2313x; 1.0419x over previous
#include <cuda_runtime.h>
#include <cuda_fp16.h>
#include <cstdint>

#define TPB 512
#define T_ 200
#define D_ 64
#define H1_ 80
#define H2_ 40
#define C_ 64

// ---- smem half-index layout ----
#define KH   0            // k fp16 [208][72]; col 64 = ones, 65-71 zero
#define KS   72
#define MTH  14976        // M^T fp16 [80][72]
#define W2H  20736        // W2^T fp16 [40][88]
#define HS   88
#define WCH  27488        // Wc fp16 [64][216] scattered softmax weights
#define WCS  216
// ---- float-index regions ----
#define CHF   7488        // CH f32 [64][72] cate numerators (aliases MTH/W2H post-GEMM)
#define CHS   72
#define QA    12128
#define PA1   12208
#define PB2   12288
#define PA2   12328
#define PWF   12368
#define WGT   12408
#define PART  12640       // [512] ui partials
#define WSF   13152       // WS f32 [64]
#define SMEM_BYTES 82624  // -> 2 CTAs/SM

// ---- device-global prepped weights ----
__device__ __align__(16) __half g_w1bc[H1_ * D_];   // (W1b - W1c)^T  [h][d]
__device__ __align__(16) __half g_w1d [H1_ * D_];   // W1d^T          [h][d]
__device__ __align__(16) __half g_w1ac[H1_ * D_];   // (W1a + W1c)^T  [h][d]
__device__ __align__(16) __half g_w2t [H2_ * HS];   // W2^T padded    [j][88]

__device__ __forceinline__ void mma16816(float* c, uint32_t a0, uint32_t a1,
                                         uint32_t a2, uint32_t a3,
                                         uint32_t b0, uint32_t b1) {
    asm volatile(
        "mma.sync.aligned.m16n8k16.row.col.f32.f16.f16.f32 "
        "{%0,%1,%2,%3}, {%4,%5,%6,%7}, {%8,%9}, {%0,%1,%2,%3};"
        : "+f"(c[0]), "+f"(c[1]), "+f"(c[2]), "+f"(c[3])
        : "r"(a0), "r"(a1), "r"(a2), "r"(a3), "r"(b0), "r"(b1));
}
__device__ __forceinline__ void ldm_x4(uint32_t* r, uint32_t addr) {
    asm volatile("ldmatrix.sync.aligned.m8n8.x4.shared.b16 {%0,%1,%2,%3}, [%4];"
        : "=r"(r[0]), "=r"(r[1]), "=r"(r[2]), "=r"(r[3]) : "r"(addr));
}
__device__ __forceinline__ void ldm_x2(uint32_t* r, uint32_t addr) {
    asm volatile("ldmatrix.sync.aligned.m8n8.x2.shared.b16 {%0,%1}, [%2];"
        : "=r"(r[0]), "=r"(r[1]) : "r"(addr));
}
__device__ __forceinline__ void ldm_x4t(uint32_t* r, uint32_t addr) {
    asm volatile("ldmatrix.sync.aligned.m8n8.x4.trans.shared.b16 {%0,%1,%2,%3}, [%4];"
        : "=r"(r[0]), "=r"(r[1]), "=r"(r[2]), "=r"(r[3]) : "r"(addr));
}
__device__ __forceinline__ void ldm_x2t(uint32_t* r, uint32_t addr) {
    asm volatile("ldmatrix.sync.aligned.m8n8.x2.trans.shared.b16 {%0,%1}, [%2];"
        : "=r"(r[0]), "=r"(r[1]) : "r"(addr));
}
__device__ __forceinline__ uint32_t sptr(const void* p) {
    return (uint32_t)__cvta_generic_to_shared(p);
}
__device__ __forceinline__ uint32_t packh2(float a, float b) {
    __half2 h = __floats2half2_rn(a, b);
    return *(uint32_t*)&h;
}

// ---------- prep kernel: batch-invariant weight transforms only ----------
__global__ void prep_w(const float* __restrict__ W1, const float* __restrict__ W2) {
    const int g = blockIdx.x * blockDim.x + threadIdx.x;
    const int stride = gridDim.x * blockDim.x;
    for (int i = g; i < H1_ * D_; i += stride) {
        const int h = i >> 6, d = i & 63;
        g_w1bc[i] = __float2half_rn(W1[(64 + d) * H1_ + h] - W1[(128 + d) * H1_ + h]);
        g_w1d[i]  = __float2half_rn(W1[(192 + d) * H1_ + h]);
        g_w1ac[i] = __float2half_rn(W1[d * H1_ + h] + W1[(128 + d) * H1_ + h]);
    }
    for (int i = g; i < H2_ * HS; i += stride) {
        const int j = i / HS, c = i - j * HS;
        g_w2t[i] = (c < H1_) ? __float2half_rn(W2[c * H2_ + j]) : __float2half_rn(0.f);
    }
}

// ---------------------------- main kernel ----------------------------
__global__ __launch_bounds__(TPB, 2)
void din_kernel(const float* __restrict__ q, const float* __restrict__ k,
                const int* __restrict__ mask, const int* __restrict__ cate,
                const float* __restrict__ b1, const float* __restrict__ a1,
                const float* __restrict__ b2, const float* __restrict__ a2,
                const float* __restrict__ Wf, const float* __restrict__ bf,
                float* __restrict__ out_ui, float* __restrict__ out_ch)
{
    extern __shared__ float sm[];
    __half* sh = (__half*)sm;
    const int b = blockIdx.x;
    const int tid = threadIdx.x;
    const int lane = tid & 31, warp = tid >> 5;
    const float* qb = q + b * D_;

    // ---------------- Phase 0: params, k->fp16, W2^T, M^T, qa, zero Wc ---------------
    if (tid < H1_) sm[PA1 + tid] = a1[tid];
    if (tid < H2_) { sm[PB2 + tid] = b2[tid]; sm[PA2 + tid] = a2[tid]; sm[PWF + tid] = Wf[tid]; }
    {   // k -> fp16 [208][72]
        const float4* k4 = (const float4*)(k + (size_t)b * T_ * D_);
        for (int idx = tid; idx < T_ * 16; idx += TPB) {
            float4 v = k4[idx];
            const int t = idx >> 4, f4 = idx & 15;
            uint2 u;
            *(__half2*)&u.x = __floats2half2_rn(v.x, v.y);
            *(__half2*)&u.y = __floats2half2_rn(v.z, v.w);
            *(uint2*)&sh[t * KS + f4 * 4] = u;
        }
        if (tid < 128) {                       // zero rows 200..207, cols 0..63
            const int t = 200 + (tid >> 4), d4 = (tid & 15) * 4;
            *(uint2*)&sh[t * KS + d4] = make_uint2(0u, 0u);
        }
        if (tid < 208)                         // ones-column pad: col64=1.0, 65-71=0
            *(uint4*)&sh[tid * KS + 64] = make_uint4(0x00003C00u, 0u, 0u, 0u);
    }
    {   // zero Wc [64][216] fp16
        uint4* wc4 = (uint4*)&sh[WCH];
        for (int i = tid; i < (C_ * WCS) / 8; i += TPB) wc4[i] = make_uint4(0u, 0u, 0u, 0u);
    }
    {   // W2^T pre-padded copy
        const uint4* w2g = (const uint4*)g_w2t;
        uint4* w2s = (uint4*)&sh[W2H];
        if (tid < 440) w2s[tid] = w2g[tid];
    }
    {   // M^T[h][d] = w1bc + q_d * w1d
        const __half2* bc2 = (const __half2*)g_w1bc;
        const __half2* dd2 = (const __half2*)g_w1d;
        for (int i2 = tid; i2 < H1_ * 32; i2 += TPB) {
            const int h = i2 >> 5, dp = i2 & 31;
            float2 bc = __half22float2(bc2[i2]);
            float2 dd = __half22float2(dd2[i2]);
            const float q0 = __ldg(qb + dp * 2), q1 = __ldg(qb + dp * 2 + 1);
            *(__half2*)&sh[MTH + h * KS + dp * 2] =
                __floats2half2_rn(fmaf(q0, dd.x, bc.x), fmaf(q1, dd.y, bc.y));
        }
    }
    if (tid < 320) {   // qa[h] = b1[h] + q . w1ac[h]
        const int h = tid >> 2, qq = tid & 3;
        const __half2* ac2 = (const __half2*)(g_w1ac + h * 64 + qq * 16);
        float s = 0.f;
#pragma unroll
        for (int p = 0; p < 8; ++p) {
            float2 f = __half22float2(ac2[p]);
            s += __ldg(qb + qq * 16 + 2 * p) * f.x + __ldg(qb + qq * 16 + 2 * p + 1) * f.y;
        }
        s += __shfl_xor_sync(0xffffffffu, s, 1);
        s += __shfl_xor_sync(0xffffffffu, s, 2);
        if (qq == 0) sm[QA + h] = s + b1[h];
    }
    __syncthreads();

    // ------- Fused GEMM1 -> PReLU -> GEMM2 -> logits (register-resident) -------
    if (warp < 13) {
        const int mt = warp;
        const int r = lane >> 2, qd = lane & 3;
        const uint32_t a_base  = sptr(&sh[(mt * 16 + (lane & 15)) * KS + ((lane >> 4) << 3)]);
        const uint32_t b1_base = sptr(&sh[MTH + (((lane >> 4) << 3) + (lane & 7)) * KS
                                              + (((lane >> 3) & 1) << 3)]);
        const uint32_t b2_base = sptr(&sh[W2H + (((lane >> 4) << 3) + (lane & 7)) * HS
                                              + (((lane >> 3) & 1) << 3)]);
        float acc2[5][4];
#pragma unroll
        for (int jn = 0; jn < 5; ++jn)
#pragma unroll
            for (int x = 0; x < 4; ++x) acc2[jn][x] = 0.f;

#pragma unroll
        for (int np = 0; np < 5; ++np) {
            float alo[4] = {0.f, 0.f, 0.f, 0.f};
            float ahi[4] = {0.f, 0.f, 0.f, 0.f};
#pragma unroll
            for (int kk = 0; kk < 4; ++kk) {
                uint32_t af[4], bp[4];
                ldm_x4(af, a_base + kk * 32);
                ldm_x4(bp, b1_base + (uint32_t)(np * 16 * KS * 2) + kk * 32);
                mma16816(alo, af[0], af[1], af[2], af[3], bp[0], bp[1]);
                mma16816(ahi, af[0], af[1], af[2], af[3], bp[2], bp[3]);
            }
            const int jl = np * 16 + qd * 2, jh = jl + 8;
            const float ql0 = sm[QA + jl],  ql1 = sm[QA + jl + 1];
            const float ll0 = sm[PA1 + jl], ll1 = sm[PA1 + jl + 1];
            const float qh0 = sm[QA + jh],  qh1 = sm[QA + jh + 1];
            const float lh0 = sm[PA1 + jh], lh1 = sm[PA1 + jh + 1];
            float v0 = alo[0] + ql0; v0 = (v0 > 0.f) ? v0 : v0 * ll0;
            float v1 = alo[1] + ql1; v1 = (v1 > 0.f) ? v1 : v1 * ll1;
            float v2 = alo[2] + ql0; v2 = (v2 > 0.f) ? v2 : v2 * ll0;
            float v3 = alo[3] + ql1; v3 = (v3 > 0.f) ? v3 : v3 * ll1;
            float w0 = ahi[0] + qh0; w0 = (w0 > 0.f) ? w0 : w0 * lh0;
            float w1 = ahi[1] + qh1; w1 = (w1 > 0.f) ? w1 : w1 * lh1;
            float w2 = ahi[2] + qh0; w2 = (w2 > 0.f) ? w2 : w2 * lh0;
            float w3 = ahi[3] + qh1; w3 = (w3 > 0.f) ? w3 : w3 * lh1;
            const uint32_t A0 = packh2(v0, v1);
            const uint32_t A1 = packh2(v2, v3);
            const uint32_t A2 = packh2(w0, w1);
            const uint32_t A3 = packh2(w2, w3);
            uint32_t b01[4], b23[4], b4[2];
            const uint32_t bb = b2_base + np * 32;
            ldm_x4(b01, bb);
            ldm_x4(b23, bb + 2u * 8 * HS * 2);
            ldm_x2(b4,  bb + 4u * 8 * HS * 2);
            mma16816(acc2[0], A0, A1, A2, A3, b01[0], b01[1]);
            mma16816(acc2[1], A0, A1, A2, A3, b01[2], b01[3]);
            mma16816(acc2[2], A0, A1, A2, A3, b23[0], b23[1]);
            mma16816(acc2[3], A0, A1, A2, A3, b23[2], b23[3]);
            mma16816(acc2[4], A0, A1, A2, A3, b4[0],  b4[1]);
        }
        float slo = 0.f, shi = 0.f;
#pragma unroll
        for (int jn = 0; jn < 5; ++jn) {
            const int j = jn * 8 + qd * 2;
            const float bb0 = sm[PB2 + j], bb1 = sm[PB2 + j + 1];
            const float al0 = sm[PA2 + j], al1 = sm[PA2 + j + 1];
            const float wf0 = sm[PWF + j], wf1 = sm[PWF + j + 1];
            float x0 = acc2[jn][0] + bb0; x0 = (x0 > 0.f) ? x0 : x0 * al0;
            float x1 = acc2[jn][1] + bb1; x1 = (x1 > 0.f) ? x1 : x1 * al1;
            float x2 = acc2[jn][2] + bb0; x2 = (x2 > 0.f) ? x2 : x2 * al0;
            float x3 = acc2[jn][3] + bb1; x3 = (x3 > 0.f) ? x3 : x3 * al1;
            slo += x0 * wf0 + x1 * wf1;
            shi += x2 * wf0 + x3 * wf1;
        }
        slo += __shfl_xor_sync(0xffffffffu, slo, 1);
        slo += __shfl_xor_sync(0xffffffffu, slo, 2);
        shi += __shfl_xor_sync(0xffffffffu, shi, 1);
        shi += __shfl_xor_sync(0xffffffffu, shi, 2);
        if (qd == 0) {
            const float bff = bf[0];
            const int t0 = mt * 16 + r, t1 = t0 + 8;
            if (t0 < T_) {
                float s = slo + bff;
                if (mask[b * T_ + t0] == 0) s = -4294967295.0f;
                sm[WGT + t0] = s * 0.125f;
            }
            if (t1 < T_) {
                float s = shi + bff;
                if (mask[b * T_ + t1] == 0) s = -4294967295.0f;
                sm[WGT + t1] = s * 0.125f;
            }
        }
    }
    __syncthreads();

    // ------- Softmax (warp-redundant, barrier-free) + scatter w into Wc -------
    {
        float mx = -3.4e38f, sv = 0.f;
        float vals[7];
#pragma unroll
        for (int j = 0; j < 7; ++j) {
            const int t = lane + 32 * j;
            vals[j] = (t < T_) ? sm[WGT + t] : -3.4e38f;
            mx = fmaxf(mx, vals[j]);
        }
#pragma unroll
        for (int o = 16; o; o >>= 1) mx = fmaxf(mx, __shfl_xor_sync(0xffffffffu, mx, o));
#pragma unroll
        for (int j = 0; j < 7; ++j)
            sv += (lane + 32 * j < T_) ? __expf(vals[j] - mx) : 0.f;
#pragma unroll
        for (int o = 16; o; o >>= 1) sv += __shfl_xor_sync(0xffffffffu, sv, o);
        const float inv = 1.0f / sv;
        if (tid < T_) {
            const float w = __expf(sm[WGT + tid] - mx) * inv;
            const int ct = cate[b * T_ + tid];
            sh[WCH + ct * WCS + tid] = __float2half_rn(w);
        }
    }
    __syncthreads();

    // ------- Cate GEMM (HMMA): CH = Wc @ k  (N=72; col 64 = ws) -------
    if (warp < 12) {
        const int mt = warp & 3, g = warp >> 2;
        const int r = lane >> 2, qd = lane & 3;
        const int n0 = g * 24;
        const uint32_t aw_base = sptr(&sh[WCH + (mt * 16 + (lane & 15)) * WCS
                                              + ((lane >> 4) << 3)]);
        const int krow = (lane & 7) + ((lane >> 3) & 1) * 8;
        const uint32_t bt4_base = sptr(&sh[krow * KS + n0 + ((lane >> 4) << 3)]);
        const uint32_t bt2_base = sptr(&sh[krow * KS + n0 + 16]);
        float acc[3][4];
#pragma unroll
        for (int j = 0; j < 3; ++j)
#pragma unroll
            for (int x = 0; x < 4; ++x) acc[j][x] = 0.f;
#pragma unroll
        for (int kc = 0; kc < 13; ++kc) {
            uint32_t af[4], bt[4], b2r[2];
            ldm_x4 (af,  aw_base  + kc * 32);
            ldm_x4t(bt,  bt4_base + (uint32_t)(kc * 16 * KS * 2));
            ldm_x2t(b2r, bt2_base + (uint32_t)(kc * 16 * KS * 2));
            mma16816(acc[0], af[0], af[1], af[2], af[3], bt[0], bt[1]);
            mma16816(acc[1], af[0], af[1], af[2], af[3], bt[2], bt[3]);
            mma16816(acc[2], af[0], af[1], af[2], af[3], b2r[0], b2r[1]);
        }
        const int c0 = mt * 16 + r;
#pragma unroll
        for (int j = 0; j < 3; ++j) {
            const int col = n0 + j * 8 + qd * 2;
            if (col < 64) {
                sm[CHF + c0 * CHS + col]           = acc[j][0];
                sm[CHF + c0 * CHS + col + 1]       = acc[j][1];
                sm[CHF + (c0 + 8) * CHS + col]     = acc[j][2];
                sm[CHF + (c0 + 8) * CHS + col + 1] = acc[j][3];
            } else if (col == 64) {
                sm[WSF + c0]     = acc[j][0];
                sm[WSF + c0 + 8] = acc[j][2];
            }
        }
    }
    __syncthreads();

    // ------- Normalize + store cate_hidden; ui[d] = sum_c CH[c][d] -------
    {
        const int g = tid >> 6, d = tid & 63;
        float s = 0.f;
#pragma unroll
        for (int c = g * 8; c < g * 8 + 8; ++c) s += sm[CHF + c * CHS + d];
        sm[PART + tid] = s;

        float* ch = out_ch + (size_t)b * C_ * D_;
#pragma unroll
        for (int i = tid; i < C_ * D_; i += TPB) {
            const int c = i >> 6, dd = i & 63;
            ch[i] = sm[CHF + c * CHS + dd] / (sm[WSF + c] + 1e-10f);
        }
    }
    __syncthreads();
    if (tid < D_) {
        float s = 0.f;
#pragma unroll
        for (int g = 0; g < 8; ++g) s += sm[PART + g * 64 + tid];
        out_ui[b * D_ + tid] = s;
    }
}

extern "C" void kernel_launch(void* const* d_in, const int* in_sizes, int n_in,
                              void* d_out, int out_size)
{
    const float* q    = (const float*)d_in[0];
    const float* k    = (const float*)d_in[1];
    const int*   mask = (const int*)d_in[2];
    const int*   cate = (const int*)d_in[3];
    // d_in[4] = cate_count (compile-time C_=64)
    const float* W1 = (const float*)d_in[5];
    const float* b1 = (const float*)d_in[6];
    const float* a1 = (const float*)d_in[7];
    const float* W2 = (const float*)d_in[8];
    const float* b2 = (const float*)d_in[9];
    const float* a2 = (const float*)d_in[10];
    const float* Wf = (const float*)d_in[11];
    const float* bf = (const float*)d_in[12];

    const int B = in_sizes[0] / D_;
    float* out_ui = (float*)d_out;                     // [B, 64]
    float* out_ch = (float*)d_out + (size_t)B * D_;    // [B, 64, 64]

    prep_w<<<8, 256>>>(W1, W2);

    cudaFuncSetAttribute(din_kernel, cudaFuncAttributeMaxDynamicSharedMemorySize, SMEM_BYTES);
    din_kernel<<<B, TPB, SMEM_BYTES>>>(q, k, mask, cate, b1, a1, b2, a2, Wf, bf,
                                       out_ui, out_ch);
}

// round 13
// speedup vs baseline: 2.3246x; 1.0418x over previous
#include <cuda_runtime.h>
#include <cuda_fp16.h>
#include <cstdint>

#define TPB 416
#define T_ 200
#define D_ 64
#define H1_ 80
#define H2_ 40
#define C_ 64

// ---- smem half-index layout ----
#define KH   0            // k fp16 [208][72]; cols 64-71 zero
#define KS   72
#define WCH  14976        // Wc fp16 [64][216] (zero-filled AFTER fused GEMM)
#define WCS  216
#define MTH  14976        // M^T fp16 [80][72]   — aliases Wc, dead after fused GEMM
#define W2H  20736        // W2^T fp16 [40][88]  — aliases Wc, dead after fused GEMM
#define HS   88
// ---- float-index tail (starts at half 28800) ----
#define QA    14400
#define PA1   14480
#define PB2   14560
#define PA2   14600
#define PWF   14640
#define WGT   14680
#define PART  14880       // [72] ui numerator accumulators
#define WSF   14952       // [64] ws accumulators
#define SMEM_FLOATS 15016
#define SMEM_BYTES (SMEM_FLOATS * 4)   // 60,064 B -> 3 CTAs/SM

// ---- device-global prepped weights ----
__device__ __align__(16) __half g_w1bc[H1_ * D_];   // (W1b - W1c)^T  [h][d]
__device__ __align__(16) __half g_w1d [H1_ * D_];   // W1d^T          [h][d]
__device__ __align__(16) __half g_w1ac[H1_ * D_];   // (W1a + W1c)^T  [h][d]
__device__ __align__(16) __half g_w2t [H2_ * HS];   // W2^T padded    [j][88]

__device__ __forceinline__ void mma16816(float* c, uint32_t a0, uint32_t a1,
                                         uint32_t a2, uint32_t a3,
                                         uint32_t b0, uint32_t b1) {
    asm volatile(
        "mma.sync.aligned.m16n8k16.row.col.f32.f16.f16.f32 "
        "{%0,%1,%2,%3}, {%4,%5,%6,%7}, {%8,%9}, {%0,%1,%2,%3};"
        : "+f"(c[0]), "+f"(c[1]), "+f"(c[2]), "+f"(c[3])
        : "r"(a0), "r"(a1), "r"(a2), "r"(a3), "r"(b0), "r"(b1));
}
__device__ __forceinline__ void ldm_x4(uint32_t* r, uint32_t addr) {
    asm volatile("ldmatrix.sync.aligned.m8n8.x4.shared.b16 {%0,%1,%2,%3}, [%4];"
        : "=r"(r[0]), "=r"(r[1]), "=r"(r[2]), "=r"(r[3]) : "r"(addr));
}
__device__ __forceinline__ void ldm_x2(uint32_t* r, uint32_t addr) {
    asm volatile("ldmatrix.sync.aligned.m8n8.x2.shared.b16 {%0,%1}, [%2];"
        : "=r"(r[0]), "=r"(r[1]) : "r"(addr));
}
__device__ __forceinline__ void ldm_x4t(uint32_t* r, uint32_t addr) {
    asm volatile("ldmatrix.sync.aligned.m8n8.x4.trans.shared.b16 {%0,%1,%2,%3}, [%4];"
        : "=r"(r[0]), "=r"(r[1]), "=r"(r[2]), "=r"(r[3]) : "r"(addr));
}
__device__ __forceinline__ void ldm_x2t(uint32_t* r, uint32_t addr) {
    asm volatile("ldmatrix.sync.aligned.m8n8.x2.trans.shared.b16 {%0,%1}, [%2];"
        : "=r"(r[0]), "=r"(r[1]) : "r"(addr));
}
__device__ __forceinline__ uint32_t sptr(const void* p) {
    return (uint32_t)__cvta_generic_to_shared(p);
}
__device__ __forceinline__ uint32_t packh2(float a, float b) {
    __half2 h = __floats2half2_rn(a, b);
    return *(uint32_t*)&h;
}

// ---------- prep kernel: batch-invariant weight transforms only ----------
__global__ void prep_w(const float* __restrict__ W1, const float* __restrict__ W2) {
    const int g = blockIdx.x * blockDim.x + threadIdx.x;
    const int stride = gridDim.x * blockDim.x;
    for (int i = g; i < H1_ * D_; i += stride) {
        const int h = i >> 6, d = i & 63;
        g_w1bc[i] = __float2half_rn(W1[(64 + d) * H1_ + h] - W1[(128 + d) * H1_ + h]);
        g_w1d[i]  = __float2half_rn(W1[(192 + d) * H1_ + h]);
        g_w1ac[i] = __float2half_rn(W1[d * H1_ + h] + W1[(128 + d) * H1_ + h]);
    }
    for (int i = g; i < H2_ * HS; i += stride) {
        const int j = i / HS, c = i - j * HS;
        g_w2t[i] = (c < H1_) ? __float2half_rn(W2[c * H2_ + j]) : __float2half_rn(0.f);
    }
}

// ---------------------------- main kernel ----------------------------
__global__ __launch_bounds__(TPB, 3)
void din_kernel(const float* __restrict__ q, const float* __restrict__ k,
                const int* __restrict__ mask, const int* __restrict__ cate,
                const float* __restrict__ b1, const float* __restrict__ a1,
                const float* __restrict__ b2, const float* __restrict__ a2,
                const float* __restrict__ Wf, const float* __restrict__ bf,
                float* __restrict__ out_ui, float* __restrict__ out_ch)
{
    extern __shared__ float sm[];
    __half* sh = (__half*)sm;
    const int b = blockIdx.x;
    const int tid = threadIdx.x;
    const int lane = tid & 31, warp = tid >> 5;
    const float* qb = q + b * D_;

    // ---------------- Phase 0: params, k->fp16, W2^T, M^T, qa ----------------
    if (tid < H1_) sm[PA1 + tid] = a1[tid];
    if (tid < H2_) { sm[PB2 + tid] = b2[tid]; sm[PA2 + tid] = a2[tid]; sm[PWF + tid] = Wf[tid]; }
    if (tid < C_)  sm[WSF + tid] = 0.f;
    if (tid < 72)  sm[PART + tid] = 0.f;
    {   // k -> fp16 [208][72]
        const float4* k4 = (const float4*)(k + (size_t)b * T_ * D_);
        for (int idx = tid; idx < T_ * 16; idx += TPB) {
            float4 v = k4[idx];
            const int t = idx >> 4, f4 = idx & 15;
            uint2 u;
            *(__half2*)&u.x = __floats2half2_rn(v.x, v.y);
            *(__half2*)&u.y = __floats2half2_rn(v.z, v.w);
            *(uint2*)&sh[t * KS + f4 * 4] = u;
        }
        if (tid < 128) {                       // zero rows 200..207, cols 0..63
            const int t = 200 + (tid >> 4), d4 = (tid & 15) * 4;
            *(uint2*)&sh[t * KS + d4] = make_uint2(0u, 0u);
        }
        if (tid < 208)                         // zero cols 64..71 (all rows)
            *(uint4*)&sh[tid * KS + 64] = make_uint4(0u, 0u, 0u, 0u);
    }
    {   // W2^T pre-padded copy: 440 uint4
        const uint4* w2g = (const uint4*)g_w2t;
        uint4* w2s = (uint4*)&sh[W2H];
        for (int i = tid; i < 440; i += TPB) w2s[i] = w2g[i];
    }
    {   // M^T[h][d] = w1bc + q_d * w1d
        const __half2* bc2 = (const __half2*)g_w1bc;
        const __half2* dd2 = (const __half2*)g_w1d;
        for (int i2 = tid; i2 < H1_ * 32; i2 += TPB) {
            const int h = i2 >> 5, dp = i2 & 31;
            float2 bc = __half22float2(bc2[i2]);
            float2 dd = __half22float2(dd2[i2]);
            const float q0 = __ldg(qb + dp * 2), q1 = __ldg(qb + dp * 2 + 1);
            *(__half2*)&sh[MTH + h * KS + dp * 2] =
                __floats2half2_rn(fmaf(q0, dd.x, bc.x), fmaf(q1, dd.y, bc.y));
        }
    }
    if (tid < 320) {   // qa[h] = b1[h] + q . w1ac[h]
        const int h = tid >> 2, qq = tid & 3;
        const __half2* ac2 = (const __half2*)(g_w1ac + h * 64 + qq * 16);
        float s = 0.f;
#pragma unroll
        for (int p = 0; p < 8; ++p) {
            float2 f = __half22float2(ac2[p]);
            s += __ldg(qb + qq * 16 + 2 * p) * f.x + __ldg(qb + qq * 16 + 2 * p + 1) * f.y;
        }
        s += __shfl_xor_sync(0xffffffffu, s, 1);
        s += __shfl_xor_sync(0xffffffffu, s, 2);
        if (qq == 0) sm[QA + h] = s + b1[h];
    }
    __syncthreads();

    // ------- Fused GEMM1 -> PReLU -> GEMM2 -> logits (13 warps, reg-resident) -------
    {
        const int mt = warp;
        const int r = lane >> 2, qd = lane & 3;
        const uint32_t a_base  = sptr(&sh[(mt * 16 + (lane & 15)) * KS + ((lane >> 4) << 3)]);
        const uint32_t b1_base = sptr(&sh[MTH + (((lane >> 4) << 3) + (lane & 7)) * KS
                                              + (((lane >> 3) & 1) << 3)]);
        const uint32_t b2_base = sptr(&sh[W2H + (((lane >> 4) << 3) + (lane & 7)) * HS
                                              + (((lane >> 3) & 1) << 3)]);
        float acc2[5][4];
#pragma unroll
        for (int jn = 0; jn < 5; ++jn)
#pragma unroll
            for (int x = 0; x < 4; ++x) acc2[jn][x] = 0.f;

#pragma unroll
        for (int np = 0; np < 5; ++np) {
            float alo[4] = {0.f, 0.f, 0.f, 0.f};
            float ahi[4] = {0.f, 0.f, 0.f, 0.f};
#pragma unroll
            for (int kk = 0; kk < 4; ++kk) {
                uint32_t af[4], bp[4];
                ldm_x4(af, a_base + kk * 32);
                ldm_x4(bp, b1_base + (uint32_t)(np * 16 * KS * 2) + kk * 32);
                mma16816(alo, af[0], af[1], af[2], af[3], bp[0], bp[1]);
                mma16816(ahi, af[0], af[1], af[2], af[3], bp[2], bp[3]);
            }
            const int jl = np * 16 + qd * 2, jh = jl + 8;
            const float ql0 = sm[QA + jl],  ql1 = sm[QA + jl + 1];
            const float ll0 = sm[PA1 + jl], ll1 = sm[PA1 + jl + 1];
            const float qh0 = sm[QA + jh],  qh1 = sm[QA + jh + 1];
            const float lh0 = sm[PA1 + jh], lh1 = sm[PA1 + jh + 1];
            float v0 = alo[0] + ql0; v0 = (v0 > 0.f) ? v0 : v0 * ll0;
            float v1 = alo[1] + ql1; v1 = (v1 > 0.f) ? v1 : v1 * ll1;
            float v2 = alo[2] + ql0; v2 = (v2 > 0.f) ? v2 : v2 * ll0;
            float v3 = alo[3] + ql1; v3 = (v3 > 0.f) ? v3 : v3 * ll1;
            float w0 = ahi[0] + qh0; w0 = (w0 > 0.f) ? w0 : w0 * lh0;
            float w1 = ahi[1] + qh1; w1 = (w1 > 0.f) ? w1 : w1 * lh1;
            float w2 = ahi[2] + qh0; w2 = (w2 > 0.f) ? w2 : w2 * lh0;
            float w3 = ahi[3] + qh1; w3 = (w3 > 0.f) ? w3 : w3 * lh1;
            const uint32_t A0 = packh2(v0, v1);
            const uint32_t A1 = packh2(v2, v3);
            const uint32_t A2 = packh2(w0, w1);
            const uint32_t A3 = packh2(w2, w3);
            uint32_t b01[4], b23[4], b4[2];
            const uint32_t bb = b2_base + np * 32;
            ldm_x4(b01, bb);
            ldm_x4(b23, bb + 2u * 8 * HS * 2);
            ldm_x2(b4,  bb + 4u * 8 * HS * 2);
            mma16816(acc2[0], A0, A1, A2, A3, b01[0], b01[1]);
            mma16816(acc2[1], A0, A1, A2, A3, b01[2], b01[3]);
            mma16816(acc2[2], A0, A1, A2, A3, b23[0], b23[1]);
            mma16816(acc2[3], A0, A1, A2, A3, b23[2], b23[3]);
            mma16816(acc2[4], A0, A1, A2, A3, b4[0],  b4[1]);
        }
        float slo = 0.f, shi = 0.f;
#pragma unroll
        for (int jn = 0; jn < 5; ++jn) {
            const int j = jn * 8 + qd * 2;
            const float bb0 = sm[PB2 + j], bb1 = sm[PB2 + j + 1];
            const float al0 = sm[PA2 + j], al1 = sm[PA2 + j + 1];
            const float wf0 = sm[PWF + j], wf1 = sm[PWF + j + 1];
            float x0 = acc2[jn][0] + bb0; x0 = (x0 > 0.f) ? x0 : x0 * al0;
            float x1 = acc2[jn][1] + bb1; x1 = (x1 > 0.f) ? x1 : x1 * al1;
            float x2 = acc2[jn][2] + bb0; x2 = (x2 > 0.f) ? x2 : x2 * al0;
            float x3 = acc2[jn][3] + bb1; x3 = (x3 > 0.f) ? x3 : x3 * al1;
            slo += x0 * wf0 + x1 * wf1;
            shi += x2 * wf0 + x3 * wf1;
        }
        slo += __shfl_xor_sync(0xffffffffu, slo, 1);
        slo += __shfl_xor_sync(0xffffffffu, slo, 2);
        shi += __shfl_xor_sync(0xffffffffu, shi, 1);
        shi += __shfl_xor_sync(0xffffffffu, shi, 2);
        if (qd == 0) {
            const float bff = bf[0];
            const int t0 = mt * 16 + r, t1 = t0 + 8;
            if (t0 < T_) {
                float s = slo + bff;
                if (mask[b * T_ + t0] == 0) s = -4294967295.0f;
                sm[WGT + t0] = s * 0.125f;
            }
            if (t1 < T_) {
                float s = shi + bff;
                if (mask[b * T_ + t1] == 0) s = -4294967295.0f;
                sm[WGT + t1] = s * 0.125f;
            }
        }
    }
    __syncthreads();

    // ------- Softmax (warp-redundant) + zero Wc (MTH/W2H now dead) -------
    float wreg = 0.f;
    {
        float mx = -3.4e38f, sv = 0.f;
        float vals[7];
#pragma unroll
        for (int j = 0; j < 7; ++j) {
            const int t = lane + 32 * j;
            vals[j] = (t < T_) ? sm[WGT + t] : -3.4e38f;
            mx = fmaxf(mx, vals[j]);
        }
#pragma unroll
        for (int o = 16; o; o >>= 1) mx = fmaxf(mx, __shfl_xor_sync(0xffffffffu, mx, o));
#pragma unroll
        for (int j = 0; j < 7; ++j)
            sv += (lane + 32 * j < T_) ? __expf(vals[j] - mx) : 0.f;
#pragma unroll
        for (int o = 16; o; o >>= 1) sv += __shfl_xor_sync(0xffffffffu, sv, o);
        if (tid < T_) wreg = __expf(sm[WGT + tid] - mx) / sv;
    }
    {   // zero Wc [64][216] fp16 = 1728 uint4
        uint4* wc4 = (uint4*)&sh[WCH];
        for (int i = tid; i < (C_ * WCS) / 8; i += TPB) wc4[i] = make_uint4(0u, 0u, 0u, 0u);
    }
    __syncthreads();

    // ------- Scatter w into Wc + ws accumulation (fp16-rounded w for both) -------
    if (tid < T_) {
        const __half wh = __float2half_rn(wreg);
        const int ct = cate[b * T_ + tid];
        sh[WCH + ct * WCS + tid] = wh;
        atomicAdd(&sm[WSF + ct], __half2float(wh));
    }
    __syncthreads();

    // ------- Cate GEMM (HMMA): num = Wc @ k; normalize in-reg; ui partials -------
    if (warp < 12) {
        const int mt = warp & 3, g = warp >> 2;
        const int r = lane >> 2, qd = lane & 3;
        const int n0 = g * 24;
        const uint32_t aw_base = sptr(&sh[WCH + (mt * 16 + (lane & 15)) * WCS
                                              + ((lane >> 4) << 3)]);
        const int krow = (lane & 7) + ((lane >> 3) & 1) * 8;
        const uint32_t bt4_base = sptr(&sh[krow * KS + n0 + ((lane >> 4) << 3)]);
        const uint32_t bt2_base = sptr(&sh[krow * KS + n0 + 16]);
        float acc[3][4];
#pragma unroll
        for (int j = 0; j < 3; ++j)
#pragma unroll
            for (int x = 0; x < 4; ++x) acc[j][x] = 0.f;
#pragma unroll
        for (int kc = 0; kc < 13; ++kc) {
            uint32_t af[4], bt[4], b2r[2];
            ldm_x4 (af,  aw_base  + kc * 32);
            ldm_x4t(bt,  bt4_base + (uint32_t)(kc * 16 * KS * 2));
            ldm_x2t(b2r, bt2_base + (uint32_t)(kc * 16 * KS * 2));
            mma16816(acc[0], af[0], af[1], af[2], af[3], bt[0], bt[1]);
            mma16816(acc[1], af[0], af[1], af[2], af[3], bt[2], bt[3]);
            mma16816(acc[2], af[0], af[1], af[2], af[3], b2r[0], b2r[1]);
        }
        const int c0 = mt * 16 + r;
        const float inv0 = 1.0f / (sm[WSF + c0] + 1e-10f);
        const float inv1 = 1.0f / (sm[WSF + c0 + 8] + 1e-10f);
        float* ch = out_ch + (size_t)b * C_ * D_;
#pragma unroll
        for (int j = 0; j < 3; ++j) {
            const int col = n0 + j * 8 + qd * 2;
            if (col < 64) {       // uniform per (g,j): g==2,j==2 skipped entirely
                *(float2*)&ch[c0 * D_ + col] =
                    make_float2(acc[j][0] * inv0, acc[j][1] * inv0);
                *(float2*)&ch[(c0 + 8) * D_ + col] =
                    make_float2(acc[j][2] * inv1, acc[j][3] * inv1);
                float s0 = acc[j][0] + acc[j][2];
                float s1 = acc[j][1] + acc[j][3];
#pragma unroll
                for (int o = 4; o <= 16; o <<= 1) {   // reduce over r
                    s0 += __shfl_xor_sync(0xffffffffu, s0, o);
                    s1 += __shfl_xor_sync(0xffffffffu, s1, o);
                }
                if (r == 0) {
                    atomicAdd(&sm[PART + col], s0);
                    atomicAdd(&sm[PART + col + 1], s1);
                }
            }
        }
    }
    __syncthreads();

    // ------- ui[d] = sum_c numerator[c][d] -------
    if (tid < D_) out_ui[b * D_ + tid] = sm[PART + tid];
}

extern "C" void kernel_launch(void* const* d_in, const int* in_sizes, int n_in,
                              void* d_out, int out_size)
{
    const float* q    = (const float*)d_in[0];
    const float* k    = (const float*)d_in[1];
    const int*   mask = (const int*)d_in[2];
    const int*   cate = (const int*)d_in[3];
    // d_in[4] = cate_count (compile-time C_=64)
    const float* W1 = (const float*)d_in[5];
    const float* b1 = (const float*)d_in[6];
    const float* a1 = (const float*)d_in[7];
    const float* W2 = (const float*)d_in[8];
    const float* b2 = (const float*)d_in[9];
    const float* a2 = (const float*)d_in[10];
    const float* Wf = (const float*)d_in[11];
    const float* bf = (const float*)d_in[12];

    const int B = in_sizes[0] / D_;
    float* out_ui = (float*)d_out;                     // [B, 64]
    float* out_ch = (float*)d_out + (size_t)B * D_;    // [B, 64, 64]

    prep_w<<<8, 256>>>(W1, W2);

    cudaFuncSetAttribute(din_kernel, cudaFuncAttributeMaxDynamicSharedMemorySize, SMEM_BYTES);
    din_kernel<<<B, TPB, SMEM_BYTES>>>(q, k, mask, cate, b1, a1, b2, a2, Wf, bf,
                                       out_ui, out_ch);
}